// round 1
// baseline (speedup 1.0000x reference)
#include <cuda_runtime.h>
#include <math.h>

#define NN 64      // batch
#define TT 32      // timesteps
#define DA 1280    // feature channels
#define PP 16      // spatial positions (4x4)
#define HD 512     // hidden
#define WD 300     // wordvec
#define VV 32000   // vocab
#define FH 2048    // 4*HD

#define NBLK 128   // lstm grid

// ---------------- scratch (device globals; no allocation allowed) -------------
__device__ float g_Aflat[NN * HD * PP];   // [n][h][p]   2 MB
__device__ float g_h0[NN * HD];           // [n][h]
__device__ float g_xwx[NN * TT * FH];     // [n][t][4H]  16 MB  (x@Wx + b)
__device__ float g_attn[NN * HD];         // [n][h]
__device__ float g_hn[NN * TT * HD];      // [n][t][h]   4 MB
__device__ unsigned g_bar_count;
__device__ unsigned g_bar_gen;

// ---------------- grid barrier (all blocks resident by construction) ----------
__device__ __forceinline__ void grid_bar(unsigned* gen_local) {
    __syncthreads();
    if (threadIdx.x == 0) {
        unsigned gen = *gen_local;
        __threadfence();
        unsigned t = atomicAdd(&g_bar_count, 1u);
        if (t == NBLK - 1) {
            atomicExch(&g_bar_count, 0u);
            __threadfence();
            atomicAdd(&g_bar_gen, 1u);
        } else {
            while (atomicAdd(&g_bar_gen, 0u) == gen) { __nanosleep(64); }
        }
        __threadfence();
        *gen_local = gen + 1;
    }
    __syncthreads();
}

__global__ void bar_reset_kernel() {
    g_bar_count = 0u;
    g_bar_gen = 0u;
}

// ---------------- 1x1 conv projection: A_flat[n][h][p] -----------------------
// grid (64 n, 8 h-tiles of 64), 256 threads
__global__ void conv_kernel(const float* __restrict__ A,
                            const float* __restrict__ cw,
                            const float* __restrict__ cb) {
    int n = blockIdx.x;
    int hb0 = blockIdx.y * 64;
    __shared__ float As[32][PP];   // [c][p]
    __shared__ float Ws[64][32];   // [h][c]
    int tid = threadIdx.x;
    int p = tid & 15;
    int hq = tid >> 4;             // 0..15
    float acc[4] = {0.f, 0.f, 0.f, 0.f};

    for (int c0 = 0; c0 < DA; c0 += 32) {
        {   // load A tile: 32c x 16p = 512 elems, 2/thread (consecutive p)
            int idx = tid * 2;
            int c = idx >> 4, pp = idx & 15;
            const float* src = A + (size_t)(n * DA + c0 + c) * PP + pp;
            As[c][pp]     = src[0];
            As[c][pp + 1] = src[1];
        }
        {   // load W tile: 64h x 32c = 2048, 8/thread
            int hh = tid >> 2;
            int cc = (tid & 3) * 8;
            const float* src = cw + (size_t)(hb0 + hh) * DA + c0 + cc;
            #pragma unroll
            for (int i = 0; i < 8; i++) Ws[hh][cc + i] = src[i];
        }
        __syncthreads();
        #pragma unroll 8
        for (int c = 0; c < 32; c++) {
            float av = As[c][p];
            #pragma unroll
            for (int i = 0; i < 4; i++) acc[i] += Ws[hq * 4 + i][c] * av;
        }
        __syncthreads();
    }
    #pragma unroll
    for (int i = 0; i < 4; i++) {
        int h = hb0 + hq * 4 + i;
        g_Aflat[(size_t)(n * HD + h) * PP + p] = acc[i] + cb[h];
    }
}

// ---------------- h0 = mean over p ------------------------------------------
__global__ void h0_kernel() {
    int n = blockIdx.x;
    int h = threadIdx.x;
    const float4* src = (const float4*)&g_Aflat[(size_t)(n * HD + h) * PP];
    float4 a = src[0], b = src[1], c = src[2], d = src[3];
    float s = a.x + a.y + a.z + a.w + b.x + b.y + b.z + b.w
            + c.x + c.y + c.z + c.w + d.x + d.y + d.z + d.w;
    g_h0[n * HD + h] = s * (1.0f / 16.0f);
}

// ---------------- xwx = W_embed[cap] @ Wx + b --------------------------------
// grid (32 jtiles, 32 rtiles), 256 threads, BM=BN=64, BK=32, 4x4 thread tiles
__global__ void xwx_kernel(const int* __restrict__ cap,
                           const float* __restrict__ We,
                           const float* __restrict__ Wx,
                           const float* __restrict__ b) {
    int j0 = blockIdx.x * 64;
    int r0 = blockIdx.y * 64;
    __shared__ float As[32][64];   // [k][r]
    __shared__ float Bs[32][64];   // [k][j]
    int tid = threadIdx.x;
    int tm = tid >> 4;   // 0..15
    int tn = tid & 15;   // 0..15
    float acc[4][4];
    #pragma unroll
    for (int i = 0; i < 4; i++)
        #pragma unroll
        for (int q = 0; q < 4; q++) acc[i][q] = 0.f;

    for (int k0 = 0; k0 < WD; k0 += 32) {
        {   // A tile (gathered rows)
            int m = tid >> 2;
            int kl = (tid & 3) * 8;
            int row = cap[r0 + m];
            const float* src = We + (size_t)row * WD + k0 + kl;
            #pragma unroll
            for (int i = 0; i < 8; i++) {
                int kk = k0 + kl + i;
                As[kl + i][m] = (kk < WD) ? src[i] : 0.f;
            }
        }
        {   // B tile
            int k = tid >> 3;
            int jl = (tid & 7) * 8;
            const float* src = Wx + (size_t)(k0 + k) * FH + j0 + jl;
            bool ok = (k0 + k) < WD;
            #pragma unroll
            for (int i = 0; i < 8; i++) Bs[k][jl + i] = ok ? src[i] : 0.f;
        }
        __syncthreads();
        #pragma unroll
        for (int k = 0; k < 32; k++) {
            float4 av = *(const float4*)&As[k][tm * 4];
            float4 bv = *(const float4*)&Bs[k][tn * 4];
            float a4[4] = {av.x, av.y, av.z, av.w};
            float b4[4] = {bv.x, bv.y, bv.z, bv.w};
            #pragma unroll
            for (int i = 0; i < 4; i++)
                #pragma unroll
                for (int q = 0; q < 4; q++) acc[i][q] += a4[i] * b4[q];
        }
        __syncthreads();
    }
    #pragma unroll
    for (int i = 0; i < 4; i++) {
        int r = r0 + tm * 4 + i;
        #pragma unroll
        for (int q = 0; q < 4; q++) {
            int j = j0 + tn * 4 + q;
            g_xwx[(size_t)r * FH + j] = acc[i][q] + b[j];
        }
    }
}

// ---------------- persistent LSTM: 128 blocks x 128 threads ------------------
// block = (n-tile of 16) x (h-range of 16)  ->  bid = ntile*32 + hrange
// stage A (bid<64): attention for n=bid  |  stage B: gate GEMM K=1024
__global__ void lstm_kernel(const float* __restrict__ Wh,
                            const float* __restrict__ Wattn) {
    const int bid = blockIdx.x;
    const int tid = threadIdx.x;
    const int ntile = bid >> 5;          // 0..3
    const int hrange = bid & 31;         // 0..31
    const int n0 = ntile * 16;
    const int hbase = hrange * 16;

    __shared__ float c_s[16][16];        // cell state for this (ntile, hrange)
    __shared__ float a_s[16][64];        // pre-activations [n][gate*16+h]
    __shared__ float hcat_s[16][16];     // [k][n]
    __shared__ float Ws[16][64];         // [k][gate*16+h]
    // attention-stage smem
    __shared__ float hs[HD];
    __shared__ float red[8][16];
    __shared__ float es[16];
    __shared__ float ws[16];

    unsigned gen = 0;

    // init c = h0
    for (int i = tid; i < 256; i += 128) {
        int nl = i >> 4, hl = i & 15;
        c_s[nl][hl] = g_h0[(n0 + nl) * HD + hbase + hl];
    }

    const int trow = tid >> 4;           // 0..7  -> n pair
    const int tcol = tid & 15;           // 0..15 -> j quad
    const int tg = tcol >> 2;            // gate
    const int th4 = (tcol & 3) * 4;      // h offset within range

    for (int t = 0; t < TT; t++) {
        // ---------- stage A: attention (one block per n) ----------
        if (bid < NN) {
            int n = bid;
            const float* hp = (t == 0) ? (g_h0 + n * HD)
                                       : (g_hn + (size_t)(n * TT + (t - 1)) * HD);
            for (int i = tid; i < HD; i += 128) hs[i] = hp[i];
            __syncthreads();
            {   // score partials: p = tid&15, h-slice = tid>>4 (8 slices of 64)
                int p = tid & 15, sl = tid >> 4;
                float s = 0.f;
                const float* af = g_Aflat + (size_t)(n * HD + sl * 64) * PP + p;
                #pragma unroll 4
                for (int h = 0; h < 64; h++) s += hs[sl * 64 + h] * af[h * PP];
                red[sl][p] = s;
            }
            __syncthreads();
            if (tid < 16) {
                float s = 0.f;
                #pragma unroll
                for (int i = 0; i < 8; i++) s += red[i][tid];
                red[0][tid] = s * 0.044194173824159216f;  // 1/sqrt(512)
            }
            __syncthreads();
            if (tid < 16) {
                float m = red[0][0];
                #pragma unroll
                for (int i = 1; i < 16; i++) m = fmaxf(m, red[0][i]);
                es[tid] = expf(red[0][tid] - m);
            }
            __syncthreads();
            if (tid < 16) {
                float ssum = 0.f;
                #pragma unroll
                for (int i = 0; i < 16; i++) ssum += es[i];
                ws[tid] = es[tid] / ssum;
            }
            __syncthreads();
            {   // attn[n][h] = sum_p Aflat[n][h][p] * w[p] ; thread -> 4 h
                float4 w0 = *(const float4*)&ws[0];
                float4 w1 = *(const float4*)&ws[4];
                float4 w2 = *(const float4*)&ws[8];
                float4 w3 = *(const float4*)&ws[12];
                #pragma unroll
                for (int i = 0; i < 4; i++) {
                    int h = tid * 4 + i;
                    const float4* af = (const float4*)(g_Aflat + (size_t)(n * HD + h) * PP);
                    float4 x0 = af[0], x1 = af[1], x2 = af[2], x3 = af[3];
                    float s = x0.x * w0.x + x0.y * w0.y + x0.z * w0.z + x0.w * w0.w
                            + x1.x * w1.x + x1.y * w1.y + x1.z * w1.z + x1.w * w1.w
                            + x2.x * w2.x + x2.y * w2.y + x2.z * w2.z + x2.w * w2.w
                            + x3.x * w3.x + x3.y * w3.y + x3.z * w3.z + x3.w * w3.w;
                    g_attn[n * HD + h] = s;
                }
            }
        }
        grid_bar(&gen);

        // ---------- stage B: a = [h;attn] @ [Wh;Wattn] (+ xwx) ----------
        float acc00 = 0.f, acc01 = 0.f, acc02 = 0.f, acc03 = 0.f;
        float acc10 = 0.f, acc11 = 0.f, acc12 = 0.f, acc13 = 0.f;

        for (int c0 = 0; c0 < 2 * HD; c0 += 16) {
            {   // stage hcat_s[k][n]: 256 elems, 2/thread, coalesced in k
                int nl = tid >> 3;
                int kl = (tid & 7) * 2;
                int n = n0 + nl;
                int kk = c0 + kl;
                const float* src;
                int off;
                if (kk < HD) {
                    src = (t == 0) ? (g_h0 + n * HD)
                                   : (g_hn + (size_t)(n * TT + (t - 1)) * HD);
                    off = kk;
                } else {
                    src = g_attn + n * HD;
                    off = kk - HD;
                }
                hcat_s[kl][nl]     = src[off];
                hcat_s[kl + 1][nl] = src[off + 1];
            }
            {   // stage Ws[k][jj]: 1024 elems, 8/thread
                int k = tid >> 3;
                int jl0 = (tid & 7) * 8;
                int kk = c0 + k;
                const float* Wsrc = (kk < HD) ? (Wh + (size_t)kk * FH)
                                              : (Wattn + (size_t)(kk - HD) * FH);
                #pragma unroll
                for (int i = 0; i < 8; i++) {
                    int jj = jl0 + i;
                    int g = jj >> 4, hh = jj & 15;
                    Ws[k][jj] = Wsrc[g * HD + hbase + hh];
                }
            }
            __syncthreads();
            #pragma unroll
            for (int k = 0; k < 16; k++) {
                float2 hv = *(const float2*)&hcat_s[k][trow * 2];
                float4 wv = *(const float4*)&Ws[k][tcol * 4];
                acc00 += hv.x * wv.x; acc01 += hv.x * wv.y;
                acc02 += hv.x * wv.z; acc03 += hv.x * wv.w;
                acc10 += hv.y * wv.x; acc11 += hv.y * wv.y;
                acc12 += hv.y * wv.z; acc13 += hv.y * wv.w;
            }
            __syncthreads();
        }

        {   // add xwx (contains x@Wx + b) and park in a_s
            #pragma unroll
            for (int i = 0; i < 2; i++) {
                int n = n0 + trow * 2 + i;
                const float* xw = g_xwx + (size_t)(n * TT + t) * FH + tg * HD + hbase + th4;
                float* dst = &a_s[trow * 2 + i][tg * 16 + th4];
                if (i == 0) {
                    dst[0] = acc00 + xw[0]; dst[1] = acc01 + xw[1];
                    dst[2] = acc02 + xw[2]; dst[3] = acc03 + xw[3];
                } else {
                    dst[0] = acc10 + xw[0]; dst[1] = acc11 + xw[1];
                    dst[2] = acc12 + xw[2]; dst[3] = acc13 + xw[3];
                }
            }
        }
        __syncthreads();

        // gates + state update; write h into [n][t][h] history
        for (int pair = tid; pair < 256; pair += 128) {
            int nl = pair >> 4, hl = pair & 15;
            float ai = a_s[nl][hl];
            float af_ = a_s[nl][16 + hl];
            float ao = a_s[nl][32 + hl];
            float ag = a_s[nl][48 + hl];
            float ig = 1.f / (1.f + expf(-ai));
            float fg = 1.f / (1.f + expf(-af_));
            float og = 1.f / (1.f + expf(-ao));
            float gg = tanhf(ag);
            float c = fg * c_s[nl][hl] + ig * gg;
            c_s[nl][hl] = c;
            float hv = og * tanhf(c);
            g_hn[(size_t)((n0 + nl) * TT + t) * HD + hbase + hl] = hv;
        }
        grid_bar(&gen);
    }
}

// ---------------- vocab GEMM: [2048,512] @ [512,32000] + bias ----------------
// BM=BN=128, BK=8, 256 threads, 8x8 register tiles
__global__ void vocab_kernel(const float* __restrict__ Wv,
                             const float* __restrict__ bv,
                             float* __restrict__ out) {
    int bx = blockIdx.x;   // 0..249 (cols)
    int by = blockIdx.y;   // 0..15  (rows)
    __shared__ float As[8][128];
    __shared__ float Bs[8][128];
    int tid = threadIdx.x;
    int tm = tid >> 4;     // 0..15
    int tn = tid & 15;     // 0..15

    float acc[8][8];
    #pragma unroll
    for (int i = 0; i < 8; i++)
        #pragma unroll
        for (int j = 0; j < 8; j++) acc[i][j] = 0.f;

    for (int k0 = 0; k0 < HD; k0 += 8) {
        {   // A: 128 rows x 8 k; 2 threads per row, float4 each
            int row = tid >> 1;
            int kq = (tid & 1) * 4;
            float4 v = *(const float4*)(g_hn + (size_t)(by * 128 + row) * HD + k0 + kq);
            As[kq + 0][row] = v.x;
            As[kq + 1][row] = v.y;
            As[kq + 2][row] = v.z;
            As[kq + 3][row] = v.w;
        }
        {   // B: 8 k x 128 cols
            int kr = tid >> 5;
            int cq = (tid & 31) * 4;
            *(float4*)&Bs[kr][cq] =
                *(const float4*)(Wv + (size_t)(k0 + kr) * VV + bx * 128 + cq);
        }
        __syncthreads();
        #pragma unroll
        for (int k = 0; k < 8; k++) {
            float4 a0 = *(const float4*)&As[k][tm * 8];
            float4 a1 = *(const float4*)&As[k][tm * 8 + 4];
            float4 b0 = *(const float4*)&Bs[k][tn * 8];
            float4 b1 = *(const float4*)&Bs[k][tn * 8 + 4];
            float av[8] = {a0.x, a0.y, a0.z, a0.w, a1.x, a1.y, a1.z, a1.w};
            float bw[8] = {b0.x, b0.y, b0.z, b0.w, b1.x, b1.y, b1.z, b1.w};
            #pragma unroll
            for (int i = 0; i < 8; i++)
                #pragma unroll
                for (int j = 0; j < 8; j++) acc[i][j] += av[i] * bw[j];
        }
        __syncthreads();
    }

    #pragma unroll
    for (int i = 0; i < 8; i++) {
        int r = by * 128 + tm * 8 + i;
        float* o = out + (size_t)r * VV + bx * 128 + tn * 8;
        const float* bvp = bv + bx * 128 + tn * 8;
        #pragma unroll
        for (int j = 0; j < 8; j++) o[j] = acc[i][j] + bvp[j];
    }
}

// ---------------- launch ------------------------------------------------------
extern "C" void kernel_launch(void* const* d_in, const int* in_sizes, int n_in,
                              void* d_out, int out_size) {
    const float* A      = (const float*)d_in[0];
    const int*   cap    = (const int*)d_in[1];
    const float* conv_w = (const float*)d_in[2];
    const float* conv_b = (const float*)d_in[3];
    const float* Wx     = (const float*)d_in[4];
    const float* Wh     = (const float*)d_in[5];
    const float* Wattn  = (const float*)d_in[6];
    const float* b      = (const float*)d_in[7];
    const float* We     = (const float*)d_in[8];
    const float* Wv     = (const float*)d_in[9];
    const float* bv     = (const float*)d_in[10];
    float* out = (float*)d_out;

    conv_kernel<<<dim3(64, 8), 256>>>(A, conv_w, conv_b);
    h0_kernel<<<64, 512>>>();
    xwx_kernel<<<dim3(32, 32), 256>>>(cap, We, Wx, b);
    bar_reset_kernel<<<1, 1>>>();
    lstm_kernel<<<NBLK, 128>>>(Wh, Wattn);
    vocab_kernel<<<dim3(250, 16), 256>>>(Wv, bv, out);
}

// round 2
// speedup vs baseline: 1.3193x; 1.3193x over previous
#include <cuda_runtime.h>
#include <math.h>

#define NN 64      // batch
#define TT 32      // timesteps
#define DA 1280    // feature channels
#define PP 16      // spatial positions (4x4)
#define HD 512     // hidden
#define WD 300     // wordvec
#define VV 32000   // vocab
#define FH 2048    // 4*HD

#define NBLK 128   // lstm grid

// ---------------- scratch (device globals; no allocation allowed) -------------
__device__ float g_Aflat[NN * HD * PP];   // [n][h][p]   2 MB
__device__ float g_h0[NN * HD];           // [n][h]
__device__ float g_xwx[NN * TT * FH];     // [n][t][4H]  16 MB  (x@Wx + b)
__device__ float g_attn[NN * HD];         // [n][h]
__device__ float g_hn[NN * TT * HD];      // [n][t][h]   4 MB
__device__ unsigned g_bar_count;
__device__ unsigned g_bar_gen;

// ---------------- grid barrier (all blocks resident by construction) ----------
__device__ __forceinline__ void grid_bar(unsigned* gen_local) {
    __syncthreads();
    if (threadIdx.x == 0) {
        unsigned gen = *gen_local;
        __threadfence();
        unsigned t = atomicAdd(&g_bar_count, 1u);
        if (t == NBLK - 1) {
            atomicExch(&g_bar_count, 0u);
            __threadfence();
            atomicAdd(&g_bar_gen, 1u);
        } else {
            while (atomicAdd(&g_bar_gen, 0u) == gen) { __nanosleep(64); }
        }
        __threadfence();
        *gen_local = gen + 1;
    }
    __syncthreads();
}

__device__ __forceinline__ unsigned f2tf32(float x) {
    unsigned r;
    asm("cvt.rna.tf32.f32 %0, %1;" : "=r"(r) : "f"(x));
    return r;
}

// ---------------- 1x1 conv projection + h0 mean + barrier reset --------------
// grid (64 n, 8 h-tiles of 64), 256 threads
__global__ void conv_kernel(const float* __restrict__ A,
                            const float* __restrict__ cw,
                            const float* __restrict__ cb) {
    if (blockIdx.x == 0 && blockIdx.y == 0 && threadIdx.x == 0) {
        g_bar_count = 0u;
        g_bar_gen = 0u;
    }
    int n = blockIdx.x;
    int hb0 = blockIdx.y * 64;
    __shared__ float As[32][PP];   // [c][p]
    __shared__ float Ws[64][32];   // [h][c]
    int tid = threadIdx.x;
    int p = tid & 15;
    int hq = tid >> 4;             // 0..15
    float acc[4] = {0.f, 0.f, 0.f, 0.f};

    for (int c0 = 0; c0 < DA; c0 += 32) {
        {   // load A tile: 32c x 16p = 512 elems, 2/thread (consecutive p)
            int idx = tid * 2;
            int c = idx >> 4, pp = idx & 15;
            const float* src = A + (size_t)(n * DA + c0 + c) * PP + pp;
            As[c][pp]     = src[0];
            As[c][pp + 1] = src[1];
        }
        {   // load W tile: 64h x 32c = 2048, 8/thread
            int hh = tid >> 2;
            int cc = (tid & 3) * 8;
            const float* src = cw + (size_t)(hb0 + hh) * DA + c0 + cc;
            #pragma unroll
            for (int i = 0; i < 8; i++) Ws[hh][cc + i] = src[i];
        }
        __syncthreads();
        #pragma unroll 8
        for (int c = 0; c < 32; c++) {
            float av = As[c][p];
            #pragma unroll
            for (int i = 0; i < 4; i++) acc[i] += Ws[hq * 4 + i][c] * av;
        }
        __syncthreads();
    }
    #pragma unroll
    for (int i = 0; i < 4; i++) {
        int h = hb0 + hq * 4 + i;
        float v = acc[i] + cb[h];
        g_Aflat[(size_t)(n * HD + h) * PP + p] = v;
        // mean over the 16 p-lanes (lanes 0-15 / 16-31 are disjoint hq halves)
        float s = v;
        #pragma unroll
        for (int m = 1; m < 16; m <<= 1) s += __shfl_xor_sync(0xffffffffu, s, m);
        if (p == 0) g_h0[n * HD + h] = s * (1.0f / 16.0f);
    }
}

// ---------------- xwx = W_embed[cap] @ Wx + b --------------------------------
// grid (32 jtiles, 32 rtiles), 256 threads, BM=BN=64, BK=32, 4x4 thread tiles
__global__ void xwx_kernel(const int* __restrict__ cap,
                           const float* __restrict__ We,
                           const float* __restrict__ Wx,
                           const float* __restrict__ b) {
    int j0 = blockIdx.x * 64;
    int r0 = blockIdx.y * 64;
    __shared__ float As[32][64];   // [k][r]
    __shared__ float Bs[32][64];   // [k][j]
    int tid = threadIdx.x;
    int tm = tid >> 4;   // 0..15
    int tn = tid & 15;   // 0..15
    float acc[4][4];
    #pragma unroll
    for (int i = 0; i < 4; i++)
        #pragma unroll
        for (int q = 0; q < 4; q++) acc[i][q] = 0.f;

    for (int k0 = 0; k0 < WD; k0 += 32) {
        {   // A tile (gathered rows)
            int m = tid >> 2;
            int kl = (tid & 3) * 8;
            int row = cap[r0 + m];
            const float* src = We + (size_t)row * WD + k0 + kl;
            #pragma unroll
            for (int i = 0; i < 8; i++) {
                int kk = k0 + kl + i;
                As[kl + i][m] = (kk < WD) ? src[i] : 0.f;
            }
        }
        {   // B tile
            int k = tid >> 3;
            int jl = (tid & 7) * 8;
            const float* src = Wx + (size_t)(k0 + k) * FH + j0 + jl;
            bool ok = (k0 + k) < WD;
            #pragma unroll
            for (int i = 0; i < 8; i++) Bs[k][jl + i] = ok ? src[i] : 0.f;
        }
        __syncthreads();
        #pragma unroll
        for (int k = 0; k < 32; k++) {
            float4 av = *(const float4*)&As[k][tm * 4];
            float4 bv = *(const float4*)&Bs[k][tn * 4];
            float a4[4] = {av.x, av.y, av.z, av.w};
            float b4[4] = {bv.x, bv.y, bv.z, bv.w};
            #pragma unroll
            for (int i = 0; i < 4; i++)
                #pragma unroll
                for (int q = 0; q < 4; q++) acc[i][q] += a4[i] * b4[q];
        }
        __syncthreads();
    }
    #pragma unroll
    for (int i = 0; i < 4; i++) {
        int r = r0 + tm * 4 + i;
        #pragma unroll
        for (int q = 0; q < 4; q++) {
            int j = j0 + tn * 4 + q;
            g_xwx[(size_t)r * FH + j] = acc[i][q] + b[j];
        }
    }
}

// ---------------- persistent LSTM: 128 blocks x 128 threads ------------------
__global__ void lstm_kernel(const float* __restrict__ Wh,
                            const float* __restrict__ Wattn) {
    const int bid = blockIdx.x;
    const int tid = threadIdx.x;
    const int ntile = bid >> 5;          // 0..3
    const int hrange = bid & 31;         // 0..31
    const int n0 = ntile * 16;
    const int hbase = hrange * 16;

    __shared__ float c_s[16][16];        // cell state for this (ntile, hrange)
    __shared__ float a_s[16][64];        // pre-activations [n][gate*16+h]
    __shared__ float hcat_s[16][16];     // [k][n]
    __shared__ float Ws[16][64];         // [k][gate*16+h]
    // attention-stage smem
    __shared__ float hs[HD];
    __shared__ float red[8][16];
    __shared__ float es[16];
    __shared__ float ws[16];

    unsigned gen = 0;

    // init c = h0
    for (int i = tid; i < 256; i += 128) {
        int nl = i >> 4, hl = i & 15;
        c_s[nl][hl] = g_h0[(n0 + nl) * HD + hbase + hl];
    }

    const int trow = tid >> 4;           // 0..7  -> n pair
    const int tcol = tid & 15;           // 0..15 -> j quad
    const int tg = tcol >> 2;            // gate
    const int th4 = (tcol & 3) * 4;      // h offset within range

    for (int t = 0; t < TT; t++) {
        // ---------- stage A: attention (one block per n) ----------
        if (bid < NN) {
            int n = bid;
            const float* hp = (t == 0) ? (g_h0 + n * HD)
                                       : (g_hn + (size_t)(n * TT + (t - 1)) * HD);
            for (int i = tid; i < HD; i += 128) hs[i] = hp[i];
            __syncthreads();
            {   // score partials: p = tid&15, h-slice = tid>>4 (8 slices of 64)
                int p = tid & 15, sl = tid >> 4;
                float s = 0.f;
                const float* af = g_Aflat + (size_t)(n * HD + sl * 64) * PP + p;
                #pragma unroll 4
                for (int h = 0; h < 64; h++) s += hs[sl * 64 + h] * af[h * PP];
                red[sl][p] = s;
            }
            __syncthreads();
            if (tid < 16) {
                float s = 0.f;
                #pragma unroll
                for (int i = 0; i < 8; i++) s += red[i][tid];
                red[0][tid] = s * 0.044194173824159216f;  // 1/sqrt(512)
            }
            __syncthreads();
            if (tid < 16) {
                float m = red[0][0];
                #pragma unroll
                for (int i = 1; i < 16; i++) m = fmaxf(m, red[0][i]);
                es[tid] = expf(red[0][tid] - m);
            }
            __syncthreads();
            if (tid < 16) {
                float ssum = 0.f;
                #pragma unroll
                for (int i = 0; i < 16; i++) ssum += es[i];
                ws[tid] = es[tid] / ssum;
            }
            __syncthreads();
            {   // attn[n][h] = sum_p Aflat[n][h][p] * w[p] ; thread -> 4 h
                float4 w0 = *(const float4*)&ws[0];
                float4 w1 = *(const float4*)&ws[4];
                float4 w2 = *(const float4*)&ws[8];
                float4 w3 = *(const float4*)&ws[12];
                #pragma unroll
                for (int i = 0; i < 4; i++) {
                    int h = tid * 4 + i;
                    const float4* af = (const float4*)(g_Aflat + (size_t)(n * HD + h) * PP);
                    float4 x0 = af[0], x1 = af[1], x2 = af[2], x3 = af[3];
                    float s = x0.x * w0.x + x0.y * w0.y + x0.z * w0.z + x0.w * w0.w
                            + x1.x * w1.x + x1.y * w1.y + x1.z * w1.z + x1.w * w1.w
                            + x2.x * w2.x + x2.y * w2.y + x2.z * w2.z + x2.w * w2.w
                            + x3.x * w3.x + x3.y * w3.y + x3.z * w3.z + x3.w * w3.w;
                    g_attn[n * HD + h] = s;
                }
            }
        }
        grid_bar(&gen);

        // ---------- stage B: a = [h;attn] @ [Wh;Wattn] (+ xwx) ----------
        float acc00 = 0.f, acc01 = 0.f, acc02 = 0.f, acc03 = 0.f;
        float acc10 = 0.f, acc11 = 0.f, acc12 = 0.f, acc13 = 0.f;

        for (int c0 = 0; c0 < 2 * HD; c0 += 16) {
            {   // stage hcat_s[k][n]
                int nl = tid >> 3;
                int kl = (tid & 7) * 2;
                int n = n0 + nl;
                int kk = c0 + kl;
                const float* src;
                int off;
                if (kk < HD) {
                    src = (t == 0) ? (g_h0 + n * HD)
                                   : (g_hn + (size_t)(n * TT + (t - 1)) * HD);
                    off = kk;
                } else {
                    src = g_attn + n * HD;
                    off = kk - HD;
                }
                hcat_s[kl][nl]     = src[off];
                hcat_s[kl + 1][nl] = src[off + 1];
            }
            {   // stage Ws[k][jj]
                int k = tid >> 3;
                int jl0 = (tid & 7) * 8;
                int kk = c0 + k;
                const float* Wsrc = (kk < HD) ? (Wh + (size_t)kk * FH)
                                              : (Wattn + (size_t)(kk - HD) * FH);
                #pragma unroll
                for (int i = 0; i < 8; i++) {
                    int jj = jl0 + i;
                    int g = jj >> 4, hh = jj & 15;
                    Ws[k][jj] = Wsrc[g * HD + hbase + hh];
                }
            }
            __syncthreads();
            #pragma unroll
            for (int k = 0; k < 16; k++) {
                float2 hv = *(const float2*)&hcat_s[k][trow * 2];
                float4 wv = *(const float4*)&Ws[k][tcol * 4];
                acc00 += hv.x * wv.x; acc01 += hv.x * wv.y;
                acc02 += hv.x * wv.z; acc03 += hv.x * wv.w;
                acc10 += hv.y * wv.x; acc11 += hv.y * wv.y;
                acc12 += hv.y * wv.z; acc13 += hv.y * wv.w;
            }
            __syncthreads();
        }

        {   // add xwx (contains x@Wx + b) and park in a_s
            #pragma unroll
            for (int i = 0; i < 2; i++) {
                int n = n0 + trow * 2 + i;
                const float* xw = g_xwx + (size_t)(n * TT + t) * FH + tg * HD + hbase + th4;
                float* dst = &a_s[trow * 2 + i][tg * 16 + th4];
                if (i == 0) {
                    dst[0] = acc00 + xw[0]; dst[1] = acc01 + xw[1];
                    dst[2] = acc02 + xw[2]; dst[3] = acc03 + xw[3];
                } else {
                    dst[0] = acc10 + xw[0]; dst[1] = acc11 + xw[1];
                    dst[2] = acc12 + xw[2]; dst[3] = acc13 + xw[3];
                }
            }
        }
        __syncthreads();

        // gates + state update; write h into [n][t][h] history
        for (int pair = tid; pair < 256; pair += 128) {
            int nl = pair >> 4, hl = pair & 15;
            float ai = a_s[nl][hl];
            float af_ = a_s[nl][16 + hl];
            float ao = a_s[nl][32 + hl];
            float ag = a_s[nl][48 + hl];
            float ig = 1.f / (1.f + expf(-ai));
            float fg = 1.f / (1.f + expf(-af_));
            float og = 1.f / (1.f + expf(-ao));
            float gg = tanhf(ag);
            float c = fg * c_s[nl][hl] + ig * gg;
            c_s[nl][hl] = c;
            float hv = og * tanhf(c);
            g_hn[(size_t)((n0 + nl) * TT + t) * HD + hbase + hl] = hv;
        }
        grid_bar(&gen);
    }
}

// ---------------- vocab GEMM via tf32 mma.sync -------------------------------
// C[2048,32000] = hn[2048,512] @ Wv[512,32000] + bv
// block tile 128x128, BK=32; 8 warps in 4(M) x 2(N); warp tile 32x64
#define VSTR 136   // smem row stride (floats): (8*ct+gr)%32 bijective -> no conflicts
__global__ void vocab_mma_kernel(const float* __restrict__ Wv,
                                 const float* __restrict__ bv,
                                 float* __restrict__ out) {
    __shared__ float As[32][VSTR];   // [k][m]  tf32-rounded
    __shared__ float Bs[32][VSTR];   // [k][n]  tf32-rounded

    const int tid = threadIdx.x;
    const int bx = blockIdx.x;       // 0..249 col tiles
    const int by = blockIdx.y;       // 0..15  row tiles
    const int warp = tid >> 5;
    const int lane = tid & 31;
    const int wm = (warp & 3) * 32;  // warp M offset
    const int wn = (warp >> 2) * 64; // warp N offset
    const int gr = lane >> 2;        // 0..7
    const int ct = lane & 3;         // 0..3

    float acc[2][8][4];
    #pragma unroll
    for (int i = 0; i < 2; i++)
        #pragma unroll
        for (int j = 0; j < 8; j++)
            #pragma unroll
            for (int q = 0; q < 4; q++) acc[i][j][q] = 0.f;

    const int arow = tid >> 1;             // 0..127
    const int akq  = (tid & 1) * 4;        // 0 or 4
    const int bkr  = tid >> 3;             // 0..31
    const int bnb  = (tid & 7) * 16;       // 0..112

    for (int k0 = 0; k0 < HD; k0 += 32) {
        {   // A: 128 rows x 32 k, 16 el/thread (4x float4 at k strides of 8)
            const float* ap = g_hn + (size_t)(by * 128 + arow) * HD + k0 + akq;
            #pragma unroll
            for (int c = 0; c < 4; c++) {
                float4 v = *(const float4*)(ap + c * 8);
                int kk = akq + c * 8;
                As[kk + 0][arow] = __uint_as_float(f2tf32(v.x));
                As[kk + 1][arow] = __uint_as_float(f2tf32(v.y));
                As[kk + 2][arow] = __uint_as_float(f2tf32(v.z));
                As[kk + 3][arow] = __uint_as_float(f2tf32(v.w));
            }
        }
        {   // B: 32 k x 128 n, 16 el/thread
            const float* bp = Wv + (size_t)(k0 + bkr) * VV + bx * 128 + bnb;
            #pragma unroll
            for (int c = 0; c < 4; c++) {
                float4 v = *(const float4*)(bp + c * 4);
                float4 w;
                w.x = __uint_as_float(f2tf32(v.x));
                w.y = __uint_as_float(f2tf32(v.y));
                w.z = __uint_as_float(f2tf32(v.z));
                w.w = __uint_as_float(f2tf32(v.w));
                *(float4*)&Bs[bkr][bnb + c * 4] = w;
            }
        }
        __syncthreads();

        #pragma unroll
        for (int ks = 0; ks < 4; ks++) {
            const int kb = ks * 8;
            unsigned a[2][4], bfr[8][2];
            #pragma unroll
            for (int i = 0; i < 2; i++) {
                const int mb = wm + i * 16;
                a[i][0] = __float_as_uint(As[kb + ct][mb + gr]);
                a[i][1] = __float_as_uint(As[kb + ct][mb + gr + 8]);
                a[i][2] = __float_as_uint(As[kb + ct + 4][mb + gr]);
                a[i][3] = __float_as_uint(As[kb + ct + 4][mb + gr + 8]);
            }
            #pragma unroll
            for (int j = 0; j < 8; j++) {
                const int nb = wn + j * 8;
                bfr[j][0] = __float_as_uint(Bs[kb + ct][nb + gr]);
                bfr[j][1] = __float_as_uint(Bs[kb + ct + 4][nb + gr]);
            }
            #pragma unroll
            for (int i = 0; i < 2; i++)
                #pragma unroll
                for (int j = 0; j < 8; j++) {
                    asm volatile(
                        "mma.sync.aligned.m16n8k8.row.col.f32.tf32.tf32.f32 "
                        "{%0,%1,%2,%3}, {%4,%5,%6,%7}, {%8,%9}, {%0,%1,%2,%3};\n"
                        : "+f"(acc[i][j][0]), "+f"(acc[i][j][1]),
                          "+f"(acc[i][j][2]), "+f"(acc[i][j][3])
                        : "r"(a[i][0]), "r"(a[i][1]), "r"(a[i][2]), "r"(a[i][3]),
                          "r"(bfr[j][0]), "r"(bfr[j][1]));
                }
        }
        __syncthreads();
    }

    // epilogue: c0=(gr,2ct), c1=(gr,2ct+1), c2=(gr+8,2ct), c3=(gr+8,2ct+1)
    #pragma unroll
    for (int i = 0; i < 2; i++) {
        const int r0 = by * 128 + wm + i * 16 + gr;
        #pragma unroll
        for (int j = 0; j < 8; j++) {
            const int col = bx * 128 + wn + j * 8 + ct * 2;
            const float b0 = bv[col], b1 = bv[col + 1];
            float2 v0 = {acc[i][j][0] + b0, acc[i][j][1] + b1};
            float2 v1 = {acc[i][j][2] + b0, acc[i][j][3] + b1};
            *(float2*)(out + (size_t)r0 * VV + col) = v0;
            *(float2*)(out + (size_t)(r0 + 8) * VV + col) = v1;
        }
    }
}

// ---------------- launch ------------------------------------------------------
extern "C" void kernel_launch(void* const* d_in, const int* in_sizes, int n_in,
                              void* d_out, int out_size) {
    const float* A      = (const float*)d_in[0];
    const int*   cap    = (const int*)d_in[1];
    const float* conv_w = (const float*)d_in[2];
    const float* conv_b = (const float*)d_in[3];
    const float* Wx     = (const float*)d_in[4];
    const float* Wh     = (const float*)d_in[5];
    const float* Wattn  = (const float*)d_in[6];
    const float* b      = (const float*)d_in[7];
    const float* We     = (const float*)d_in[8];
    const float* Wv     = (const float*)d_in[9];
    const float* bv     = (const float*)d_in[10];
    float* out = (float*)d_out;

    conv_kernel<<<dim3(64, 8), 256>>>(A, conv_w, conv_b);
    xwx_kernel<<<dim3(32, 32), 256>>>(cap, We, Wx, b);
    lstm_kernel<<<NBLK, 128>>>(Wh, Wattn);
    vocab_mma_kernel<<<dim3(250, 16), 256>>>(Wv, bv, out);
}

// round 3
// speedup vs baseline: 1.6027x; 1.2148x over previous
#include <cuda_runtime.h>
#include <math.h>

#define NN 64      // batch
#define TT 32      // timesteps
#define DA 1280    // feature channels
#define PP 16      // spatial positions (4x4)
#define HD 512     // hidden
#define WD 300     // wordvec
#define VV 32000   // vocab
#define FH 2048    // 4*HD

#define NBLK 128   // lstm grid

// ---------------- scratch (device globals; no allocation allowed) -------------
__device__ float g_Aflat[NN * HD * PP];   // [n][h][p]   2 MB
__device__ float g_h0[NN * HD];           // [n][h]
__device__ float g_xwx[NN * TT * FH];     // [n][t][4H]  16 MB  (x@Wx + b)
__device__ float g_attn[NN * HD];         // [n][h]
__device__ float g_hn[NN * TT * HD];      // [n][t][h]   4 MB
__device__ unsigned g_bar_count;
__device__ volatile unsigned g_bar_gen;

// ---------------- grid barrier: atomic arrive, volatile-load spin -------------
__device__ __forceinline__ void grid_bar(unsigned* gen_local) {
    __syncthreads();
    if (threadIdx.x == 0) {
        unsigned gen = *gen_local;
        __threadfence();
        if (atomicAdd(&g_bar_count, 1u) == NBLK - 1u) {
            g_bar_count = 0u;
            __threadfence();
            g_bar_gen = gen + 1u;
        } else {
            while (g_bar_gen == gen) { __nanosleep(32); }
        }
        __threadfence();
        *gen_local = gen + 1u;
    }
    __syncthreads();
}

__device__ __forceinline__ unsigned f2tf32(float x) {
    unsigned r;
    asm("cvt.rna.tf32.f32 %0, %1;" : "=r"(r) : "f"(x));
    return r;
}

// ---------------- 1x1 conv projection + h0 mean + barrier reset --------------
// grid (64 n, 8 h-tiles of 64), 256 threads
__global__ void conv_kernel(const float* __restrict__ A,
                            const float* __restrict__ cw,
                            const float* __restrict__ cb) {
    if (blockIdx.x == 0 && blockIdx.y == 0 && threadIdx.x == 0) {
        g_bar_count = 0u;
        g_bar_gen = 0u;
    }
    int n = blockIdx.x;
    int hb0 = blockIdx.y * 64;
    __shared__ float As[32][PP];   // [c][p]
    __shared__ float Ws[64][32];   // [h][c]
    int tid = threadIdx.x;
    int p = tid & 15;
    int hq = tid >> 4;             // 0..15
    float acc[4] = {0.f, 0.f, 0.f, 0.f};

    for (int c0 = 0; c0 < DA; c0 += 32) {
        {
            int idx = tid * 2;
            int c = idx >> 4, pp = idx & 15;
            const float* src = A + (size_t)(n * DA + c0 + c) * PP + pp;
            As[c][pp]     = src[0];
            As[c][pp + 1] = src[1];
        }
        {
            int hh = tid >> 2;
            int cc = (tid & 3) * 8;
            const float* src = cw + (size_t)(hb0 + hh) * DA + c0 + cc;
            #pragma unroll
            for (int i = 0; i < 8; i++) Ws[hh][cc + i] = src[i];
        }
        __syncthreads();
        #pragma unroll 8
        for (int c = 0; c < 32; c++) {
            float av = As[c][p];
            #pragma unroll
            for (int i = 0; i < 4; i++) acc[i] += Ws[hq * 4 + i][c] * av;
        }
        __syncthreads();
    }
    #pragma unroll
    for (int i = 0; i < 4; i++) {
        int h = hb0 + hq * 4 + i;
        float v = acc[i] + cb[h];
        g_Aflat[(size_t)(n * HD + h) * PP + p] = v;
        float s = v;
        #pragma unroll
        for (int m = 1; m < 16; m <<= 1) s += __shfl_xor_sync(0xffffffffu, s, m);
        if (p == 0) g_h0[n * HD + h] = s * (1.0f / 16.0f);
    }
}

// ---------------- xwx = W_embed[cap] @ Wx + b --------------------------------
__global__ void xwx_kernel(const int* __restrict__ cap,
                           const float* __restrict__ We,
                           const float* __restrict__ Wx,
                           const float* __restrict__ b) {
    int j0 = blockIdx.x * 64;
    int r0 = blockIdx.y * 64;
    __shared__ float As[32][64];   // [k][r]
    __shared__ float Bs[32][64];   // [k][j]
    int tid = threadIdx.x;
    int tm = tid >> 4;
    int tn = tid & 15;
    float acc[4][4];
    #pragma unroll
    for (int i = 0; i < 4; i++)
        #pragma unroll
        for (int q = 0; q < 4; q++) acc[i][q] = 0.f;

    for (int k0 = 0; k0 < WD; k0 += 32) {
        {
            int m = tid >> 2;
            int kl = (tid & 3) * 8;
            int row = cap[r0 + m];
            const float* src = We + (size_t)row * WD + k0 + kl;
            #pragma unroll
            for (int i = 0; i < 8; i++) {
                int kk = k0 + kl + i;
                As[kl + i][m] = (kk < WD) ? src[i] : 0.f;
            }
        }
        {
            int k = tid >> 3;
            int jl = (tid & 7) * 8;
            const float* src = Wx + (size_t)(k0 + k) * FH + j0 + jl;
            bool ok = (k0 + k) < WD;
            #pragma unroll
            for (int i = 0; i < 8; i++) Bs[k][jl + i] = ok ? src[i] : 0.f;
        }
        __syncthreads();
        #pragma unroll
        for (int k = 0; k < 32; k++) {
            float4 av = *(const float4*)&As[k][tm * 4];
            float4 bv = *(const float4*)&Bs[k][tn * 4];
            float a4[4] = {av.x, av.y, av.z, av.w};
            float b4[4] = {bv.x, bv.y, bv.z, bv.w};
            #pragma unroll
            for (int i = 0; i < 4; i++)
                #pragma unroll
                for (int q = 0; q < 4; q++) acc[i][q] += a4[i] * b4[q];
        }
        __syncthreads();
    }
    #pragma unroll
    for (int i = 0; i < 4; i++) {
        int r = r0 + tm * 4 + i;
        #pragma unroll
        for (int q = 0; q < 4; q++) {
            int j = j0 + tn * 4 + q;
            g_xwx[(size_t)r * FH + j] = acc[i][q] + b[j];
        }
    }
}

// ---------------- persistent LSTM: 128 blocks x 256 threads ------------------
// block = (n-tile of 16) x (h-range of 16): bid = ntile*32 + hrange
// double-buffered staging; attention on blocks 0..63
__global__ void lstm_kernel(const float* __restrict__ Wh,
                            const float* __restrict__ Wattn) {
    const int bid = blockIdx.x;
    const int tid = threadIdx.x;
    const int ntile = bid >> 5;
    const int hrange = bid & 31;
    const int n0 = ntile * 16;
    const int hbase = hrange * 16;

    __shared__ float c_s[16][16];
    __shared__ float a_s[16][64];
    __shared__ float hcat_s[2][32][16];  // [buf][k][n]
    __shared__ float Ws_s[2][32][64];    // [buf][k][jj]
    __shared__ float hs[HD];
    __shared__ float red[16][16];
    __shared__ float es[16];
    __shared__ float wsf[16];

    unsigned gen = 0;

    // init c = h0 (each thread owns exactly the element it later updates)
    {
        int nl = tid >> 4, hl = tid & 15;
        c_s[nl][hl] = g_h0[(n0 + nl) * HD + hbase + hl];
    }

    // compute mapping: 256 threads -> 16n x 16 j-quads
    const int tn = tid >> 4;             // n local
    const int tj = tid & 15;             // j quad (jj = tj*4..tj*4+3)
    // hcat staging mapping
    const int hn_ = tid >> 4;            // n local 0..15
    const int hk  = (tid & 15) * 2;      // k pair 0..30
    // Ws staging mapping
    const int swk = tid >> 3;            // k row 0..31
    const int swj = (tid & 7) * 8;       // j octet 0..56
    const int wcol0 = (swj >> 4) * HD + hbase + (swj & 15);

    for (int t = 0; t < TT; t++) {
        // ---------- stage A: attention (blocks 0..63; one per n) ----------
        if (bid < NN) {
            int n = bid;
            const float* hp = (t == 0) ? (g_h0 + n * HD)
                                       : (g_hn + (size_t)(n * TT + (t - 1)) * HD);
            ((float2*)hs)[tid] = ((const float2*)hp)[tid];
            __syncthreads();
            {   // score partials: 16 slices of 32 h x 16 p
                int p = tid & 15, sl = tid >> 4;
                float s = 0.f;
                const float* af = g_Aflat + (size_t)(n * HD + sl * 32) * PP + p;
                #pragma unroll 4
                for (int h = 0; h < 32; h++) s += hs[sl * 32 + h] * af[h * PP];
                red[sl][p] = s;
            }
            __syncthreads();
            if (tid < 16) {
                float s = 0.f;
                #pragma unroll
                for (int i = 0; i < 16; i++) s += red[i][tid];
                red[0][tid] = s * 0.044194173824159216f;  // 1/sqrt(512)
            }
            __syncthreads();
            if (tid < 16) {
                float m = red[0][0];
                #pragma unroll
                for (int i = 1; i < 16; i++) m = fmaxf(m, red[0][i]);
                es[tid] = expf(red[0][tid] - m);
            }
            __syncthreads();
            if (tid < 16) {
                float ssum = 0.f;
                #pragma unroll
                for (int i = 0; i < 16; i++) ssum += es[i];
                wsf[tid] = es[tid] / ssum;
            }
            __syncthreads();
            {   // attn[n][h] = sum_p Aflat[n][h][p]*w[p]; 2 h per thread
                float4 w0 = *(const float4*)&wsf[0];
                float4 w1 = *(const float4*)&wsf[4];
                float4 w2 = *(const float4*)&wsf[8];
                float4 w3 = *(const float4*)&wsf[12];
                #pragma unroll
                for (int r = 0; r < 2; r++) {
                    int h = tid * 2 + r;
                    const float4* af = (const float4*)(g_Aflat + (size_t)(n * HD + h) * PP);
                    float4 x0 = af[0], x1 = af[1], x2 = af[2], x3 = af[3];
                    float s = x0.x * w0.x + x0.y * w0.y + x0.z * w0.z + x0.w * w0.w
                            + x1.x * w1.x + x1.y * w1.y + x1.z * w1.z + x1.w * w1.w
                            + x2.x * w2.x + x2.y * w2.y + x2.z * w2.z + x2.w * w2.w
                            + x3.x * w3.x + x3.y * w3.y + x3.z * w3.z + x3.w * w3.w;
                    g_attn[n * HD + h] = s;
                }
            }
        }
        grid_bar(&gen);

        // ---------- stage B: a = [h;attn] @ [Wh;Wattn] (+ xwx) ----------
        const float* hbase_n = (t == 0) ? (g_h0 + (n0 + hn_) * HD)
                                        : (g_hn + (size_t)((n0 + hn_) * TT + (t - 1)) * HD);
        const float* abase_n = g_attn + (n0 + hn_) * HD;

        float acc0 = 0.f, acc1 = 0.f, acc2 = 0.f, acc3 = 0.f;
        float2 hr;
        float4 wr0, wr1;

        // prologue: load tile 0
        {
            int kk = hk;
            hr = *(const float2*)&hbase_n[kk];
            const float* Wsrc = Wh + (size_t)swk * FH;
            wr0 = *(const float4*)&Wsrc[wcol0];
            wr1 = *(const float4*)&Wsrc[wcol0 + 4];
        }
        {
            hcat_s[0][hk][hn_]     = hr.x;
            hcat_s[0][hk + 1][hn_] = hr.y;
            *(float4*)&Ws_s[0][swk][swj]     = wr0;
            *(float4*)&Ws_s[0][swk][swj + 4] = wr1;
        }
        __syncthreads();

        for (int it = 0; it < 32; ++it) {
            if (it < 31) {   // prefetch next tile into registers
                int c0 = (it + 1) * 32;
                int kk = c0 + hk;
                hr = (kk < HD) ? *(const float2*)&hbase_n[kk]
                               : *(const float2*)&abase_n[kk - HD];
                int kw = c0 + swk;
                const float* Wsrc = (kw < HD) ? (Wh + (size_t)kw * FH)
                                              : (Wattn + (size_t)(kw - HD) * FH);
                wr0 = *(const float4*)&Wsrc[wcol0];
                wr1 = *(const float4*)&Wsrc[wcol0 + 4];
            }
            const int cb = it & 1;
            #pragma unroll
            for (int k = 0; k < 32; k++) {
                float h = hcat_s[cb][k][tn];
                float4 w = *(const float4*)&Ws_s[cb][k][tj * 4];
                acc0 += h * w.x; acc1 += h * w.y;
                acc2 += h * w.z; acc3 += h * w.w;
            }
            if (it < 31) {
                const int nb = (it + 1) & 1;
                hcat_s[nb][hk][hn_]     = hr.x;
                hcat_s[nb][hk + 1][hn_] = hr.y;
                *(float4*)&Ws_s[nb][swk][swj]     = wr0;
                *(float4*)&Ws_s[nb][swk][swj + 4] = wr1;
            }
            __syncthreads();
        }

        {   // add xwx (contains x@Wx + b), park in a_s
            int n = n0 + tn;
            int col0 = (tj >> 2) * HD + hbase + (tj & 3) * 4;
            float4 xw = *(const float4*)(g_xwx + (size_t)(n * TT + t) * FH + col0);
            a_s[tn][tj * 4 + 0] = acc0 + xw.x;
            a_s[tn][tj * 4 + 1] = acc1 + xw.y;
            a_s[tn][tj * 4 + 2] = acc2 + xw.z;
            a_s[tn][tj * 4 + 3] = acc3 + xw.w;
        }
        __syncthreads();

        {   // gates + state update; write h history
            int nl = tid >> 4, hl = tid & 15;
            float ai  = a_s[nl][hl];
            float af_ = a_s[nl][16 + hl];
            float ao  = a_s[nl][32 + hl];
            float ag  = a_s[nl][48 + hl];
            float ig = 1.f / (1.f + expf(-ai));
            float fg = 1.f / (1.f + expf(-af_));
            float og = 1.f / (1.f + expf(-ao));
            float gg = tanhf(ag);
            float c = fg * c_s[nl][hl] + ig * gg;
            c_s[nl][hl] = c;
            g_hn[(size_t)((n0 + nl) * TT + t) * HD + hbase + hl] = og * tanhf(c);
        }
        grid_bar(&gen);
    }
}

// ---------------- vocab GEMM via tf32 mma.sync, 128x256 tile -----------------
// C[2048,32000] = hn[2048,512] @ Wv[512,32000] + bv
// 8 warps: 2(M) x 4(N), warp tile 64x64 (MI=4, NJ=8); BK=16 double-buffered
#define ASTR 20
#define BSTR 264
#define VOC_SMEM ((2 * 128 * ASTR + 2 * 16 * BSTR) * 4)
#define AS(b, m, k) vsm[(b) * (128 * ASTR) + (m) * ASTR + (k)]
#define BS(b, k, n) vsm[2 * 128 * ASTR + (b) * (16 * BSTR) + (k) * BSTR + (n)]

__global__ __launch_bounds__(256, 1)
void vocab_mma_kernel(const float* __restrict__ Wv,
                      const float* __restrict__ bv,
                      float* __restrict__ out) {
    extern __shared__ float vsm[];
    const int tid = threadIdx.x;
    const int bx = blockIdx.x;       // 0..124
    const int by = blockIdx.y;       // 0..15
    const int warp = tid >> 5;
    const int lane = tid & 31;
    const int wm = (warp & 1) * 64;
    const int wn = (warp >> 1) * 64;
    const int gr = lane >> 2;
    const int ct = lane & 3;

    float acc[4][8][4];
    #pragma unroll
    for (int i = 0; i < 4; i++)
        #pragma unroll
        for (int j = 0; j < 8; j++)
            #pragma unroll
            for (int q = 0; q < 4; q++) acc[i][j][q] = 0.f;

    // staging mapping
    const int arow = tid >> 1;             // 0..127
    const int akq  = (tid & 1) * 8;        // 0 or 8
    const int bk   = tid >> 4;             // 0..15
    const int bnb  = (tid & 15) * 16;      // 0..240
    const float* aptr = g_hn + (size_t)(by * 128 + arow) * HD + akq;
    const float* bptr = Wv + (size_t)bk * VV + bx * 256 + bnb;

    float4 ar0, ar1, br[4];

    // prologue: load + store tile 0
    ar0 = *(const float4*)(aptr);
    ar1 = *(const float4*)(aptr + 4);
    #pragma unroll
    for (int c = 0; c < 4; c++) br[c] = *(const float4*)(bptr + c * 4);
    {
        float4 w0, w1;
        w0.x = __uint_as_float(f2tf32(ar0.x)); w0.y = __uint_as_float(f2tf32(ar0.y));
        w0.z = __uint_as_float(f2tf32(ar0.z)); w0.w = __uint_as_float(f2tf32(ar0.w));
        w1.x = __uint_as_float(f2tf32(ar1.x)); w1.y = __uint_as_float(f2tf32(ar1.y));
        w1.z = __uint_as_float(f2tf32(ar1.z)); w1.w = __uint_as_float(f2tf32(ar1.w));
        *(float4*)&AS(0, arow, akq) = w0;
        *(float4*)&AS(0, arow, akq + 4) = w1;
        #pragma unroll
        for (int c = 0; c < 4; c++) {
            float4 w;
            w.x = __uint_as_float(f2tf32(br[c].x)); w.y = __uint_as_float(f2tf32(br[c].y));
            w.z = __uint_as_float(f2tf32(br[c].z)); w.w = __uint_as_float(f2tf32(br[c].w));
            *(float4*)&BS(0, bk, bnb + c * 4) = w;
        }
    }
    __syncthreads();

    for (int it = 0; it < 32; ++it) {
        if (it < 31) {   // prefetch next K-tile
            int k0 = (it + 1) * 16;
            ar0 = *(const float4*)(aptr + k0);
            ar1 = *(const float4*)(aptr + k0 + 4);
            #pragma unroll
            for (int c = 0; c < 4; c++)
                br[c] = *(const float4*)(bptr + (size_t)k0 * VV + c * 4);
        }
        const int cb = it & 1;
        #pragma unroll
        for (int ks = 0; ks < 2; ks++) {
            const int kb = ks * 8;
            unsigned a[4][4], bb[8][2];
            #pragma unroll
            for (int i = 0; i < 4; i++) {
                const int mr = wm + i * 16 + gr;
                a[i][0] = __float_as_uint(AS(cb, mr,     kb + ct));
                a[i][1] = __float_as_uint(AS(cb, mr + 8, kb + ct));
                a[i][2] = __float_as_uint(AS(cb, mr,     kb + ct + 4));
                a[i][3] = __float_as_uint(AS(cb, mr + 8, kb + ct + 4));
            }
            #pragma unroll
            for (int j = 0; j < 8; j++) {
                const int nb = wn + j * 8 + gr;
                bb[j][0] = __float_as_uint(BS(cb, kb + ct,     nb));
                bb[j][1] = __float_as_uint(BS(cb, kb + ct + 4, nb));
            }
            #pragma unroll
            for (int i = 0; i < 4; i++)
                #pragma unroll
                for (int j = 0; j < 8; j++) {
                    asm volatile(
                        "mma.sync.aligned.m16n8k8.row.col.f32.tf32.tf32.f32 "
                        "{%0,%1,%2,%3}, {%4,%5,%6,%7}, {%8,%9}, {%0,%1,%2,%3};\n"
                        : "+f"(acc[i][j][0]), "+f"(acc[i][j][1]),
                          "+f"(acc[i][j][2]), "+f"(acc[i][j][3])
                        : "r"(a[i][0]), "r"(a[i][1]), "r"(a[i][2]), "r"(a[i][3]),
                          "r"(bb[j][0]), "r"(bb[j][1]));
                }
        }
        if (it < 31) {
            const int nb = (it + 1) & 1;
            float4 w0, w1;
            w0.x = __uint_as_float(f2tf32(ar0.x)); w0.y = __uint_as_float(f2tf32(ar0.y));
            w0.z = __uint_as_float(f2tf32(ar0.z)); w0.w = __uint_as_float(f2tf32(ar0.w));
            w1.x = __uint_as_float(f2tf32(ar1.x)); w1.y = __uint_as_float(f2tf32(ar1.y));
            w1.z = __uint_as_float(f2tf32(ar1.z)); w1.w = __uint_as_float(f2tf32(ar1.w));
            *(float4*)&AS(nb, arow, akq) = w0;
            *(float4*)&AS(nb, arow, akq + 4) = w1;
            #pragma unroll
            for (int c = 0; c < 4; c++) {
                float4 w;
                w.x = __uint_as_float(f2tf32(br[c].x)); w.y = __uint_as_float(f2tf32(br[c].y));
                w.z = __uint_as_float(f2tf32(br[c].z)); w.w = __uint_as_float(f2tf32(br[c].w));
                *(float4*)&BS(nb, bk, bnb + c * 4) = w;
            }
        }
        __syncthreads();
    }

    // epilogue: c0=(gr,2ct), c1=(gr,2ct+1), c2=(gr+8,2ct), c3=(gr+8,2ct+1)
    #pragma unroll
    for (int i = 0; i < 4; i++) {
        const int r0 = by * 128 + wm + i * 16 + gr;
        #pragma unroll
        for (int j = 0; j < 8; j++) {
            const int col = bx * 256 + wn + j * 8 + ct * 2;
            const float b0 = bv[col], b1 = bv[col + 1];
            float2 v0 = {acc[i][j][0] + b0, acc[i][j][1] + b1};
            float2 v1 = {acc[i][j][2] + b0, acc[i][j][3] + b1};
            *(float2*)(out + (size_t)r0 * VV + col) = v0;
            *(float2*)(out + (size_t)(r0 + 8) * VV + col) = v1;
        }
    }
}

// ---------------- launch ------------------------------------------------------
extern "C" void kernel_launch(void* const* d_in, const int* in_sizes, int n_in,
                              void* d_out, int out_size) {
    const float* A      = (const float*)d_in[0];
    const int*   cap    = (const int*)d_in[1];
    const float* conv_w = (const float*)d_in[2];
    const float* conv_b = (const float*)d_in[3];
    const float* Wx     = (const float*)d_in[4];
    const float* Wh     = (const float*)d_in[5];
    const float* Wattn  = (const float*)d_in[6];
    const float* b      = (const float*)d_in[7];
    const float* We     = (const float*)d_in[8];
    const float* Wv     = (const float*)d_in[9];
    const float* bv     = (const float*)d_in[10];
    float* out = (float*)d_out;

    cudaFuncSetAttribute(vocab_mma_kernel,
                         cudaFuncAttributeMaxDynamicSharedMemorySize, VOC_SMEM);

    conv_kernel<<<dim3(64, 8), 256>>>(A, conv_w, conv_b);
    xwx_kernel<<<dim3(32, 32), 256>>>(cap, We, Wx, b);
    lstm_kernel<<<NBLK, 256>>>(Wh, Wattn);
    vocab_mma_kernel<<<dim3(125, 16), 256, VOC_SMEM>>>(Wv, bv, out);
}

// round 4
// speedup vs baseline: 2.4778x; 1.5460x over previous
#include <cuda_runtime.h>
#include <math.h>

#define NN 64      // batch
#define TT 32      // timesteps
#define DA 1280    // feature channels
#define PP 16      // spatial positions (4x4)
#define HD 512     // hidden
#define WD 300     // wordvec
#define VV 32000   // vocab
#define FH 2048    // 4*HD

#define NBLK 64    // lstm grid

typedef unsigned int u32;

// ---------------- scratch (device globals; no allocation allowed) -------------
__device__ float g_Aflat[NN * HD * PP];   // [n][h][p]
__device__ float g_h0[NN * HD];           // [n][h]
__device__ float g_xwx[NN * TT * FH];     // [n][t][4H]  (x@Wx + b)
__device__ float g_hn[NN * TT * HD];      // [n][t][h]
// packed bf16-split hcat: [n][kpair] (k = 0..1023 -> 512 u32 pairs; k<512 h, k>=512 attn)
__device__ u32 g_hchi[NN * 512];
__device__ u32 g_hclo[NN * 512];
// pre-split, pre-transposed gate weights: [block b][jj 0..31][kpair 0..511]
__device__ u32 g_Wbhi[64 * 32 * 512];
__device__ u32 g_Wblo[64 * 32 * 512];
__device__ unsigned g_bar_count;
__device__ volatile unsigned g_bar_gen;

// ---------------- helpers -----------------------------------------------------
__device__ __forceinline__ u32 pack_bf16(float x0, float x1) {
    u32 r;  // low half = x0, high half = x1
    asm("cvt.rn.bf16x2.f32 %0, %1, %2;" : "=r"(r) : "f"(x1), "f"(x0));
    return r;
}
// split pair (x0,x1) into bf16 hi/lo packed u32s
__device__ __forceinline__ void split_pair(float x0, float x1, u32& hi, u32& lo) {
    hi = pack_bf16(x0, x1);
    float f0 = __uint_as_float(hi << 16);
    float f1 = __uint_as_float(hi & 0xffff0000u);
    lo = pack_bf16(x0 - f0, x1 - f1);
}
__device__ __forceinline__ unsigned f2tf32(float x) {
    unsigned r;
    asm("cvt.rna.tf32.f32 %0, %1;" : "=r"(r) : "f"(x));
    return r;
}
#define CP_ASYNC16(dst, src) \
    asm volatile("cp.async.cg.shared.global [%0], [%1], 16;" :: "r"(dst), "l"(src))
#define CP_COMMIT()  asm volatile("cp.async.commit_group;")
#define CP_WAIT1()   asm volatile("cp.async.wait_group 1;")
#define CP_WAIT0()   asm volatile("cp.async.wait_group 0;")

#define MMA_BF16(d0,d1,d2,d3,a0,a1,a2,a3,b0,b1) \
    asm volatile("mma.sync.aligned.m16n8k16.row.col.f32.bf16.bf16.f32 " \
        "{%0,%1,%2,%3}, {%4,%5,%6,%7}, {%8,%9}, {%0,%1,%2,%3};" \
        : "+f"(d0), "+f"(d1), "+f"(d2), "+f"(d3) \
        : "r"(a0), "r"(a1), "r"(a2), "r"(a3), "r"(b0), "r"(b1))

// ---------------- grid barrier -------------------------------------------------
__device__ __forceinline__ void grid_bar(unsigned* gen_local) {
    __syncthreads();
    if (threadIdx.x == 0) {
        unsigned gen = *gen_local;
        __threadfence();
        if (atomicAdd(&g_bar_count, 1u) == NBLK - 1u) {
            g_bar_count = 0u;
            __threadfence();
            g_bar_gen = gen + 1u;
        } else {
            while (g_bar_gen == gen) { __nanosleep(32); }
        }
        __threadfence();
        *gen_local = gen + 1u;
    }
    __syncthreads();
}

// ---------------- 1x1 conv projection + h0 mean (fp32 + packed) --------------
__global__ void conv_kernel(const float* __restrict__ A,
                            const float* __restrict__ cw,
                            const float* __restrict__ cb) {
    if (blockIdx.x == 0 && blockIdx.y == 0 && threadIdx.x == 0) {
        g_bar_count = 0u;
        g_bar_gen = 0u;
    }
    int n = blockIdx.x;
    int hb0 = blockIdx.y * 64;
    __shared__ float As[32][PP];
    __shared__ float Ws[64][32];
    int tid = threadIdx.x;
    int p = tid & 15;
    int hq = tid >> 4;
    float acc[4] = {0.f, 0.f, 0.f, 0.f};

    for (int c0 = 0; c0 < DA; c0 += 32) {
        {
            int idx = tid * 2;
            int c = idx >> 4, pp = idx & 15;
            const float* src = A + (size_t)(n * DA + c0 + c) * PP + pp;
            As[c][pp]     = src[0];
            As[c][pp + 1] = src[1];
        }
        {
            int hh = tid >> 2;
            int cc = (tid & 3) * 8;
            const float* src = cw + (size_t)(hb0 + hh) * DA + c0 + cc;
            #pragma unroll
            for (int i = 0; i < 8; i++) Ws[hh][cc + i] = src[i];
        }
        __syncthreads();
        #pragma unroll 8
        for (int c = 0; c < 32; c++) {
            float av = As[c][p];
            #pragma unroll
            for (int i = 0; i < 4; i++) acc[i] += Ws[hq * 4 + i][c] * av;
        }
        __syncthreads();
    }
    float mean4[4];
    #pragma unroll
    for (int i = 0; i < 4; i++) {
        int h = hb0 + hq * 4 + i;
        float v = acc[i] + cb[h];
        g_Aflat[(size_t)(n * HD + h) * PP + p] = v;
        float s = v;
        #pragma unroll
        for (int m = 1; m < 16; m <<= 1) s += __shfl_xor_sync(0xffffffffu, s, m);
        mean4[i] = s * (1.0f / 16.0f);
    }
    if (p == 0) {
        int h0i = hb0 + hq * 4;
        g_h0[n * HD + h0i + 0] = mean4[0];
        g_h0[n * HD + h0i + 1] = mean4[1];
        g_h0[n * HD + h0i + 2] = mean4[2];
        g_h0[n * HD + h0i + 3] = mean4[3];
        u32 hi, lo;
        split_pair(mean4[0], mean4[1], hi, lo);
        g_hchi[n * 512 + (h0i >> 1)] = hi;
        g_hclo[n * 512 + (h0i >> 1)] = lo;
        split_pair(mean4[2], mean4[3], hi, lo);
        g_hchi[n * 512 + (h0i >> 1) + 1] = hi;
        g_hclo[n * 512 + (h0i >> 1) + 1] = lo;
    }
}

// ---------------- xwx = W_embed[cap] @ Wx + b --------------------------------
__global__ void xwx_kernel(const int* __restrict__ cap,
                           const float* __restrict__ We,
                           const float* __restrict__ Wx,
                           const float* __restrict__ b) {
    int j0 = blockIdx.x * 64;
    int r0 = blockIdx.y * 64;
    __shared__ float As[32][64];
    __shared__ float Bs[32][64];
    int tid = threadIdx.x;
    int tm = tid >> 4;
    int tn = tid & 15;
    float acc[4][4];
    #pragma unroll
    for (int i = 0; i < 4; i++)
        #pragma unroll
        for (int q = 0; q < 4; q++) acc[i][q] = 0.f;

    for (int k0 = 0; k0 < WD; k0 += 32) {
        {
            int m = tid >> 2;
            int kl = (tid & 3) * 8;
            int row = cap[r0 + m];
            const float* src = We + (size_t)row * WD + k0 + kl;
            #pragma unroll
            for (int i = 0; i < 8; i++) {
                int kk = k0 + kl + i;
                As[kl + i][m] = (kk < WD) ? src[i] : 0.f;
            }
        }
        {
            int k = tid >> 3;
            int jl = (tid & 7) * 8;
            const float* src = Wx + (size_t)(k0 + k) * FH + j0 + jl;
            bool ok = (k0 + k) < WD;
            #pragma unroll
            for (int i = 0; i < 8; i++) Bs[k][jl + i] = ok ? src[i] : 0.f;
        }
        __syncthreads();
        #pragma unroll
        for (int k = 0; k < 32; k++) {
            float4 av = *(const float4*)&As[k][tm * 4];
            float4 bv = *(const float4*)&Bs[k][tn * 4];
            float a4[4] = {av.x, av.y, av.z, av.w};
            float b4[4] = {bv.x, bv.y, bv.z, bv.w};
            #pragma unroll
            for (int i = 0; i < 4; i++)
                #pragma unroll
                for (int q = 0; q < 4; q++) acc[i][q] += a4[i] * b4[q];
        }
        __syncthreads();
    }
    #pragma unroll
    for (int i = 0; i < 4; i++) {
        int r = r0 + tm * 4 + i;
        #pragma unroll
        for (int q = 0; q < 4; q++) {
            int j = j0 + tn * 4 + q;
            g_xwx[(size_t)r * FH + j] = acc[i][q] + b[j];
        }
    }
}

// ---------------- weight prep: split + transpose into per-block layout --------
// g_Wb*[b][jj][kp]: jj = g*8+jl <-> global col g*512 + b*8 + jl; kp = k/2
__global__ void wprep_kernel(const float* __restrict__ Wh,
                             const float* __restrict__ Wattn) {
    __shared__ float Wt[64][36];
    const int b = blockIdx.x;        // 0..63
    const int ch = blockIdx.y;       // 0..15 (64 k-rows each)
    const int tid = threadIdx.x;     // 256

    {   // load 64 k-rows x 32 cols (4 gate strips of 8)
        int kk = tid >> 2;
        int g = tid & 3;
        const float* src = (ch < 8)
            ? (Wh + (size_t)(ch * 64 + kk) * FH + g * HD + b * 8)
            : (Wattn + (size_t)((ch - 8) * 64 + kk) * FH + g * HD + b * 8);
        float4 v0 = *(const float4*)(src);
        float4 v1 = *(const float4*)(src + 4);
        *(float4*)&Wt[kk][g * 8]     = v0;
        *(float4*)&Wt[kk][g * 8 + 4] = v1;
    }
    __syncthreads();
    {   // write packed hi/lo: 32 jj x 32 kp
        int jj = tid >> 3;
        int kpl = (tid & 7) * 4;
        uint4 vh, vl;
        u32* ph = (u32*)&vh;
        u32* pl = (u32*)&vl;
        #pragma unroll
        for (int q = 0; q < 4; q++) {
            int kp = kpl + q;
            float x0 = Wt[2 * kp][jj];
            float x1 = Wt[2 * kp + 1][jj];
            split_pair(x0, x1, ph[q], pl[q]);
        }
        size_t dst = (size_t)(b * 32 + jj) * 512 + ch * 32 + kpl;
        *(uint4*)(g_Wbhi + dst) = vh;
        *(uint4*)(g_Wblo + dst) = vl;
    }
}

// ---------------- persistent LSTM: 64 blocks x 512 threads --------------------
// block b: attention for n=b; gates for ALL n, hl-slice [8b, 8b+8) x 4 gates.
// Weights resident in smem (bf16 hi/lo); hcat streamed via cp.async (2-stage).
#define OFF_BHI  0
#define OFF_BLO  16512
#define OFF_AHI  33024          // 2 bufs x 64 x 36
#define OFF_ALO  37632
#define OFF_CS   42240          // f32 [64][34]
#define OFF_CELL 44416          // f32 [512]
#define OFF_HS   44928          // f32 [512]
#define OFF_RED  45440          // f32 [512]
#define OFF_ES   45952
#define OFF_WSF  45968
#define LSTM_SMEM ((45984) * 4)

__global__ __launch_bounds__(512, 1) void lstm_kernel() {
    extern __shared__ u32 smu[];
    float* smf = (float*)smu;
    const int b = blockIdx.x;
    const int tid = threadIdx.x;
    const unsigned sbase = (unsigned)__cvta_generic_to_shared(smu);

    const int warp = tid >> 5, lane = tid & 31;
    const int wm = (warp & 3) * 16;      // C row base (batch)
    const int wn = (warp >> 2) * 8;      // C col base (j)
    const int gr = lane >> 2, ct = lane & 3;

    // preload weights into smem (hi/lo, padded stride 516)
    {
        const u32* srcH = g_Wbhi + (size_t)b * 16384;
        const u32* srcL = g_Wblo + (size_t)b * 16384;
        #pragma unroll
        for (int r = 0; r < 8; r++) {
            int idx = r * 2048 + tid * 4;
            int j = idx >> 9, kp = idx & 511;
            *(uint4*)(smu + OFF_BHI + j * 516 + kp) = *(const uint4*)(srcH + idx);
            *(uint4*)(smu + OFF_BLO + j * 516 + kp) = *(const uint4*)(srcL + idx);
        }
    }
    // cell state init: thread -> (n = tid>>3, hl = tid&7)
    {
        int n = tid >> 3, hl = tid & 7;
        smf[OFF_CELL + tid] = g_h0[n * HD + b * 8 + hl];
    }
    __syncthreads();

    // A staging mapping: thread -> (n = tid>>3, kpq = (tid&7)*4), 16B per array
    const int an = tid >> 3;
    const int akp = (tid & 7) * 4;
    const u32* aSrcHi = g_hchi + an * 512 + akp;
    const u32* aSrcLo = g_hclo + an * 512 + akp;
    const unsigned aDstHi = sbase + (OFF_AHI + an * 36 + akp) * 4;
    const unsigned aDstLo = sbase + (OFF_ALO + an * 36 + akp) * 4;

    unsigned gen = 0;

    for (int t = 0; t < TT; t++) {
        // ---------- stage A: attention for n = b ----------
        {
            const int n = b;
            const float* hp = (t == 0) ? (g_h0 + n * HD)
                                       : (g_hn + (size_t)(n * TT + (t - 1)) * HD);
            smf[OFF_HS + tid] = hp[tid];
            __syncthreads();
            {   // scores: 32 h-slices of 16 x 16 p
                int p = tid & 15, sl = tid >> 4;
                float s = 0.f;
                const float* af = g_Aflat + (size_t)(n * HD + sl * 16) * PP + p;
                const float* hv = &smf[OFF_HS + sl * 16];
                #pragma unroll 4
                for (int h = 0; h < 16; h++) s += hv[h] * af[h * PP];
                smf[OFF_RED + sl * 16 + p] = s;
            }
            __syncthreads();
            if (tid < 16) {
                float s = 0.f;
                #pragma unroll
                for (int i = 0; i < 32; i++) s += smf[OFF_RED + i * 16 + tid];
                smf[OFF_RED + tid] = s * 0.044194173824159216f;  // 1/sqrt(512)
            }
            __syncthreads();
            if (tid < 16) {
                float m = smf[OFF_RED + 0];
                #pragma unroll
                for (int i = 1; i < 16; i++) m = fmaxf(m, smf[OFF_RED + i]);
                smf[OFF_ES + tid] = expf(smf[OFF_RED + tid] - m);
            }
            __syncthreads();
            if (tid < 16) {
                float ssum = 0.f;
                #pragma unroll
                for (int i = 0; i < 16; i++) ssum += smf[OFF_ES + i];
                smf[OFF_WSF + tid] = smf[OFF_ES + tid] / ssum;
            }
            __syncthreads();
            if (tid < 256) {   // attn apply: 2 h per thread -> packed pair
                float4 w0 = *(const float4*)&smf[OFF_WSF + 0];
                float4 w1 = *(const float4*)&smf[OFF_WSF + 4];
                float4 w2 = *(const float4*)&smf[OFF_WSF + 8];
                float4 w3 = *(const float4*)&smf[OFF_WSF + 12];
                float sv[2];
                #pragma unroll
                for (int r = 0; r < 2; r++) {
                    int h = tid * 2 + r;
                    const float4* af = (const float4*)(g_Aflat + (size_t)(n * HD + h) * PP);
                    float4 x0 = af[0], x1 = af[1], x2 = af[2], x3 = af[3];
                    sv[r] = x0.x * w0.x + x0.y * w0.y + x0.z * w0.z + x0.w * w0.w
                          + x1.x * w1.x + x1.y * w1.y + x1.z * w1.z + x1.w * w1.w
                          + x2.x * w2.x + x2.y * w2.y + x2.z * w2.z + x2.w * w2.w
                          + x3.x * w3.x + x3.y * w3.y + x3.z * w3.z + x3.w * w3.w;
                }
                u32 hi, lo;
                split_pair(sv[0], sv[1], hi, lo);
                g_hchi[n * 512 + 256 + tid] = hi;
                g_hclo[n * 512 + 256 + tid] = lo;
            }
        }
        grid_bar(&gen);

        // ---------- stage B: C[64, 32] = hcat @ Wslice (bf16x3 mma) ----------
        float acc0 = 0.f, acc1 = 0.f, acc2 = 0.f, acc3 = 0.f;

        // issue tile 0 into buf 0
        CP_ASYNC16(aDstHi, aSrcHi);
        CP_ASYNC16(aDstLo, aSrcLo);
        CP_COMMIT();

        for (int it = 0; it < 16; ++it) {
            if (it < 15) {
                const unsigned boff = ((it + 1) & 1) * (2304 * 4);
                CP_ASYNC16(aDstHi + boff, aSrcHi + (it + 1) * 32);
                CP_ASYNC16(aDstLo + boff, aSrcLo + (it + 1) * 32);
                CP_COMMIT();
                CP_WAIT1();
            } else {
                CP_WAIT0();
            }
            __syncthreads();
            const u32* Ah = smu + OFF_AHI + (it & 1) * 2304;
            const u32* Al = smu + OFF_ALO + (it & 1) * 2304;
            const int r0 = (wm + gr) * 36;
            const int r1 = (wm + gr + 8) * 36;
            const int jrow = (wn + gr) * 516;
            #pragma unroll
            for (int ks = 0; ks < 4; ks++) {
                const int ab = ks * 8 + ct;
                const int kb = it * 32 + ks * 8 + ct;
                u32 ah0 = Ah[r0 + ab],     ah1 = Ah[r1 + ab];
                u32 ah2 = Ah[r0 + ab + 4], ah3 = Ah[r1 + ab + 4];
                u32 al0 = Al[r0 + ab],     al1 = Al[r1 + ab];
                u32 al2 = Al[r0 + ab + 4], al3 = Al[r1 + ab + 4];
                u32 bh0 = smu[OFF_BHI + jrow + kb];
                u32 bh1 = smu[OFF_BHI + jrow + kb + 4];
                u32 bl0 = smu[OFF_BLO + jrow + kb];
                u32 bl1 = smu[OFF_BLO + jrow + kb + 4];
                MMA_BF16(acc0, acc1, acc2, acc3, ah0, ah1, ah2, ah3, bh0, bh1);
                MMA_BF16(acc0, acc1, acc2, acc3, ah0, ah1, ah2, ah3, bl0, bl1);
                MMA_BF16(acc0, acc1, acc2, acc3, al0, al1, al2, al3, bh0, bh1);
            }
            __syncthreads();
        }

        // epilogue: park C in smem
        {
            float* C = &smf[OFF_CS];
            *(float2*)&C[(wm + gr) * 34 + wn + 2 * ct]     = make_float2(acc0, acc1);
            *(float2*)&C[(wm + gr + 8) * 34 + wn + 2 * ct] = make_float2(acc2, acc3);
        }
        __syncthreads();

        // gates: thread -> (n = tid>>3, hl = tid&7)
        {
            const int n = tid >> 3, hl = tid & 7;
            const float* C = &smf[OFF_CS + n * 34];
            const float* xw = g_xwx + (size_t)(n * TT + t) * FH + b * 8 + hl;
            float ai  = C[hl]      + xw[0];
            float af_ = C[8 + hl]  + xw[HD];
            float ao  = C[16 + hl] + xw[2 * HD];
            float ag  = C[24 + hl] + xw[3 * HD];
            float ig = 1.f / (1.f + expf(-ai));
            float fg = 1.f / (1.f + expf(-af_));
            float og = 1.f / (1.f + expf(-ao));
            float gg = tanhf(ag);
            float c = fg * smf[OFF_CELL + tid] + ig * gg;
            smf[OFF_CELL + tid] = c;
            float h = og * tanhf(c);
            g_hn[(size_t)(n * TT + t) * HD + b * 8 + hl] = h;
            // pack pairs via shfl (hl even lanes own the pair)
            float h1 = __shfl_down_sync(0xffffffffu, h, 1);
            if ((hl & 1) == 0) {
                u32 hi, lo;
                split_pair(h, h1, hi, lo);
                int kp = b * 4 + (hl >> 1);
                g_hchi[n * 512 + kp] = hi;
                g_hclo[n * 512 + kp] = lo;
            }
        }
        grid_bar(&gen);
    }
}

// ---------------- vocab GEMM via tf32 mma.sync, 128x256 tile -----------------
#define ASTR 20
#define BSTR 264
#define VOC_SMEM ((2 * 128 * ASTR + 2 * 16 * BSTR) * 4)
#define AS(bu, m, k) vsm[(bu) * (128 * ASTR) + (m) * ASTR + (k)]
#define BS(bu, k, n) vsm[2 * 128 * ASTR + (bu) * (16 * BSTR) + (k) * BSTR + (n)]

__global__ __launch_bounds__(256, 1)
void vocab_mma_kernel(const float* __restrict__ Wv,
                      const float* __restrict__ bv,
                      float* __restrict__ out) {
    extern __shared__ float vsm[];
    const int tid = threadIdx.x;
    const int bx = blockIdx.x;
    const int by = blockIdx.y;
    const int warp = tid >> 5;
    const int lane = tid & 31;
    const int wm = (warp & 1) * 64;
    const int wn = (warp >> 1) * 64;
    const int gr = lane >> 2;
    const int ct = lane & 3;

    float acc[4][8][4];
    #pragma unroll
    for (int i = 0; i < 4; i++)
        #pragma unroll
        for (int j = 0; j < 8; j++)
            #pragma unroll
            for (int q = 0; q < 4; q++) acc[i][j][q] = 0.f;

    const int arow = tid >> 1;
    const int akq  = (tid & 1) * 8;
    const int bk   = tid >> 4;
    const int bnb  = (tid & 15) * 16;
    const float* aptr = g_hn + (size_t)(by * 128 + arow) * HD + akq;
    const float* bptr = Wv + (size_t)bk * VV + bx * 256 + bnb;

    float4 ar0, ar1, br[4];

    ar0 = *(const float4*)(aptr);
    ar1 = *(const float4*)(aptr + 4);
    #pragma unroll
    for (int c = 0; c < 4; c++) br[c] = *(const float4*)(bptr + c * 4);
    {
        float4 w0, w1;
        w0.x = __uint_as_float(f2tf32(ar0.x)); w0.y = __uint_as_float(f2tf32(ar0.y));
        w0.z = __uint_as_float(f2tf32(ar0.z)); w0.w = __uint_as_float(f2tf32(ar0.w));
        w1.x = __uint_as_float(f2tf32(ar1.x)); w1.y = __uint_as_float(f2tf32(ar1.y));
        w1.z = __uint_as_float(f2tf32(ar1.z)); w1.w = __uint_as_float(f2tf32(ar1.w));
        *(float4*)&AS(0, arow, akq) = w0;
        *(float4*)&AS(0, arow, akq + 4) = w1;
        #pragma unroll
        for (int c = 0; c < 4; c++) {
            float4 w;
            w.x = __uint_as_float(f2tf32(br[c].x)); w.y = __uint_as_float(f2tf32(br[c].y));
            w.z = __uint_as_float(f2tf32(br[c].z)); w.w = __uint_as_float(f2tf32(br[c].w));
            *(float4*)&BS(0, bk, bnb + c * 4) = w;
        }
    }
    __syncthreads();

    for (int it = 0; it < 32; ++it) {
        if (it < 31) {
            int k0 = (it + 1) * 16;
            ar0 = *(const float4*)(aptr + k0);
            ar1 = *(const float4*)(aptr + k0 + 4);
            #pragma unroll
            for (int c = 0; c < 4; c++)
                br[c] = *(const float4*)(bptr + (size_t)k0 * VV + c * 4);
        }
        const int cb = it & 1;
        #pragma unroll
        for (int ks = 0; ks < 2; ks++) {
            const int kb = ks * 8;
            unsigned a[4][4], bb[8][2];
            #pragma unroll
            for (int i = 0; i < 4; i++) {
                const int mr = wm + i * 16 + gr;
                a[i][0] = __float_as_uint(AS(cb, mr,     kb + ct));
                a[i][1] = __float_as_uint(AS(cb, mr + 8, kb + ct));
                a[i][2] = __float_as_uint(AS(cb, mr,     kb + ct + 4));
                a[i][3] = __float_as_uint(AS(cb, mr + 8, kb + ct + 4));
            }
            #pragma unroll
            for (int j = 0; j < 8; j++) {
                const int nb = wn + j * 8 + gr;
                bb[j][0] = __float_as_uint(BS(cb, kb + ct,     nb));
                bb[j][1] = __float_as_uint(BS(cb, kb + ct + 4, nb));
            }
            #pragma unroll
            for (int i = 0; i < 4; i++)
                #pragma unroll
                for (int j = 0; j < 8; j++) {
                    asm volatile(
                        "mma.sync.aligned.m16n8k8.row.col.f32.tf32.tf32.f32 "
                        "{%0,%1,%2,%3}, {%4,%5,%6,%7}, {%8,%9}, {%0,%1,%2,%3};\n"
                        : "+f"(acc[i][j][0]), "+f"(acc[i][j][1]),
                          "+f"(acc[i][j][2]), "+f"(acc[i][j][3])
                        : "r"(a[i][0]), "r"(a[i][1]), "r"(a[i][2]), "r"(a[i][3]),
                          "r"(bb[j][0]), "r"(bb[j][1]));
                }
        }
        if (it < 31) {
            const int nb = (it + 1) & 1;
            float4 w0, w1;
            w0.x = __uint_as_float(f2tf32(ar0.x)); w0.y = __uint_as_float(f2tf32(ar0.y));
            w0.z = __uint_as_float(f2tf32(ar0.z)); w0.w = __uint_as_float(f2tf32(ar0.w));
            w1.x = __uint_as_float(f2tf32(ar1.x)); w1.y = __uint_as_float(f2tf32(ar1.y));
            w1.z = __uint_as_float(f2tf32(ar1.z)); w1.w = __uint_as_float(f2tf32(ar1.w));
            *(float4*)&AS(nb, arow, akq) = w0;
            *(float4*)&AS(nb, arow, akq + 4) = w1;
            #pragma unroll
            for (int c = 0; c < 4; c++) {
                float4 w;
                w.x = __uint_as_float(f2tf32(br[c].x)); w.y = __uint_as_float(f2tf32(br[c].y));
                w.z = __uint_as_float(f2tf32(br[c].z)); w.w = __uint_as_float(f2tf32(br[c].w));
                *(float4*)&BS(nb, bk, bnb + c * 4) = w;
            }
        }
        __syncthreads();
    }

    #pragma unroll
    for (int i = 0; i < 4; i++) {
        const int r0 = by * 128 + wm + i * 16 + gr;
        #pragma unroll
        for (int j = 0; j < 8; j++) {
            const int col = bx * 256 + wn + j * 8 + ct * 2;
            const float b0 = bv[col], b1 = bv[col + 1];
            float2 v0 = {acc[i][j][0] + b0, acc[i][j][1] + b1};
            float2 v1 = {acc[i][j][2] + b0, acc[i][j][3] + b1};
            *(float2*)(out + (size_t)r0 * VV + col) = v0;
            *(float2*)(out + (size_t)(r0 + 8) * VV + col) = v1;
        }
    }
}

// ---------------- launch ------------------------------------------------------
extern "C" void kernel_launch(void* const* d_in, const int* in_sizes, int n_in,
                              void* d_out, int out_size) {
    const float* A      = (const float*)d_in[0];
    const int*   cap    = (const int*)d_in[1];
    const float* conv_w = (const float*)d_in[2];
    const float* conv_b = (const float*)d_in[3];
    const float* Wx     = (const float*)d_in[4];
    const float* Wh     = (const float*)d_in[5];
    const float* Wattn  = (const float*)d_in[6];
    const float* b      = (const float*)d_in[7];
    const float* We     = (const float*)d_in[8];
    const float* Wv     = (const float*)d_in[9];
    const float* bv     = (const float*)d_in[10];
    float* out = (float*)d_out;

    cudaFuncSetAttribute(vocab_mma_kernel,
                         cudaFuncAttributeMaxDynamicSharedMemorySize, VOC_SMEM);
    cudaFuncSetAttribute(lstm_kernel,
                         cudaFuncAttributeMaxDynamicSharedMemorySize, LSTM_SMEM);

    conv_kernel<<<dim3(64, 8), 256>>>(A, conv_w, conv_b);
    xwx_kernel<<<dim3(32, 32), 256>>>(cap, We, Wx, b);
    wprep_kernel<<<dim3(64, 16), 256>>>(Wh, Wattn);
    lstm_kernel<<<NBLK, 512, LSTM_SMEM>>>();
    vocab_mma_kernel<<<dim3(125, 16), 256, VOC_SMEM>>>(Wv, bv, out);
}

// round 5
// speedup vs baseline: 2.5481x; 1.0284x over previous
#include <cuda_runtime.h>
#include <math.h>

#define NN 64      // batch
#define TT 32      // timesteps
#define DA 1280    // feature channels
#define PP 16      // spatial positions (4x4)
#define HD 512     // hidden
#define WD 300     // wordvec
#define VV 32000   // vocab
#define FH 2048    // 4*HD

#define NBLK 64    // lstm grid

typedef unsigned int u32;

// ---------------- scratch (device globals; no allocation allowed) -------------
__device__ float g_Aflat[NN * HD * PP];   // [n][h][p]
__device__ float g_h0[NN * HD];           // [n][h]
__device__ float g_xwx[NN * TT * FH];     // [n][t][4H]  (x@Wx + b)
__device__ float g_hn[NN * TT * HD];      // [n][t][h]
// packed bf16-split hcat: [n][kpair]; kp<256 = h, kp>=256 = attn
__device__ u32 g_hchi[NN * 512];
__device__ u32 g_hclo[NN * 512];
// pre-split, pre-transposed gate weights: [block b][jj 0..31][kpair 0..511]
__device__ u32 g_Wbhi[64 * 32 * 512];
__device__ u32 g_Wblo[64 * 32 * 512];
// xwx operand splits: X = We[cap] [2048][160 kp], WxT [2048 j][160 kp]
__device__ u32 g_Xhi[2048 * 160];
__device__ u32 g_Xlo[2048 * 160];
__device__ u32 g_WXhi[2048 * 160];
__device__ u32 g_WXlo[2048 * 160];
__device__ unsigned g_bar_count;
__device__ volatile unsigned g_bar_gen;

// ---------------- helpers -----------------------------------------------------
__device__ __forceinline__ u32 pack_bf16(float x0, float x1) {
    u32 r;  // low half = x0, high half = x1
    asm("cvt.rn.bf16x2.f32 %0, %1, %2;" : "=r"(r) : "f"(x1), "f"(x0));
    return r;
}
__device__ __forceinline__ void split_pair(float x0, float x1, u32& hi, u32& lo) {
    hi = pack_bf16(x0, x1);
    float f0 = __uint_as_float(hi << 16);
    float f1 = __uint_as_float(hi & 0xffff0000u);
    lo = pack_bf16(x0 - f0, x1 - f1);
}
__device__ __forceinline__ unsigned f2tf32(float x) {
    unsigned r;
    asm("cvt.rna.tf32.f32 %0, %1;" : "=r"(r) : "f"(x));
    return r;
}
#define CP_ASYNC16(dst, src) \
    asm volatile("cp.async.cg.shared.global [%0], [%1], 16;" :: "r"(dst), "l"(src))
#define CP_COMMIT()  asm volatile("cp.async.commit_group;")
#define CP_WAIT0()   asm volatile("cp.async.wait_group 0;")

#define MMA_BF16(d0,d1,d2,d3,a0,a1,a2,a3,b0,b1) \
    asm volatile("mma.sync.aligned.m16n8k16.row.col.f32.bf16.bf16.f32 " \
        "{%0,%1,%2,%3}, {%4,%5,%6,%7}, {%8,%9}, {%0,%1,%2,%3};" \
        : "+f"(d0), "+f"(d1), "+f"(d2), "+f"(d3) \
        : "r"(a0), "r"(a1), "r"(a2), "r"(a3), "r"(b0), "r"(b1))

#define LDSM4(r0,r1,r2,r3,addr) \
    asm volatile("ldmatrix.sync.aligned.m8n8.x4.shared.b16 {%0,%1,%2,%3}, [%4];" \
        : "=r"(r0), "=r"(r1), "=r"(r2), "=r"(r3) : "r"(addr))

// ---------------- grid barrier -------------------------------------------------
__device__ __forceinline__ void grid_bar(unsigned* gen_local) {
    __syncthreads();
    if (threadIdx.x == 0) {
        unsigned gen = *gen_local;
        __threadfence();
        if (atomicAdd(&g_bar_count, 1u) == NBLK - 1u) {
            g_bar_count = 0u;
            __threadfence();
            g_bar_gen = gen + 1u;
        } else {
            while (g_bar_gen == gen) { __nanosleep(32); }
        }
        __threadfence();
        *gen_local = gen + 1u;
    }
    __syncthreads();
}

// ---------------- 1x1 conv projection + h0 mean (fp32 + packed) --------------
__global__ void conv_kernel(const float* __restrict__ A,
                            const float* __restrict__ cw,
                            const float* __restrict__ cb) {
    if (blockIdx.x == 0 && blockIdx.y == 0 && threadIdx.x == 0) {
        g_bar_count = 0u;
        g_bar_gen = 0u;
    }
    int n = blockIdx.x;
    int hb0 = blockIdx.y * 64;
    __shared__ float As[32][PP];
    __shared__ float Ws[64][32];
    int tid = threadIdx.x;
    int p = tid & 15;
    int hq = tid >> 4;
    float acc[4] = {0.f, 0.f, 0.f, 0.f};

    for (int c0 = 0; c0 < DA; c0 += 32) {
        {
            int idx = tid * 2;
            int c = idx >> 4, pp = idx & 15;
            const float* src = A + (size_t)(n * DA + c0 + c) * PP + pp;
            As[c][pp]     = src[0];
            As[c][pp + 1] = src[1];
        }
        {
            int hh = tid >> 2;
            int cc = (tid & 3) * 8;
            const float* src = cw + (size_t)(hb0 + hh) * DA + c0 + cc;
            #pragma unroll
            for (int i = 0; i < 8; i++) Ws[hh][cc + i] = src[i];
        }
        __syncthreads();
        #pragma unroll 8
        for (int c = 0; c < 32; c++) {
            float av = As[c][p];
            #pragma unroll
            for (int i = 0; i < 4; i++) acc[i] += Ws[hq * 4 + i][c] * av;
        }
        __syncthreads();
    }
    float mean4[4];
    #pragma unroll
    for (int i = 0; i < 4; i++) {
        int h = hb0 + hq * 4 + i;
        float v = acc[i] + cb[h];
        g_Aflat[(size_t)(n * HD + h) * PP + p] = v;
        float s = v;
        #pragma unroll
        for (int m = 1; m < 16; m <<= 1) s += __shfl_xor_sync(0xffffffffu, s, m);
        mean4[i] = s * (1.0f / 16.0f);
    }
    if (p == 0) {
        int h0i = hb0 + hq * 4;
        g_h0[n * HD + h0i + 0] = mean4[0];
        g_h0[n * HD + h0i + 1] = mean4[1];
        g_h0[n * HD + h0i + 2] = mean4[2];
        g_h0[n * HD + h0i + 3] = mean4[3];
        u32 hi, lo;
        split_pair(mean4[0], mean4[1], hi, lo);
        g_hchi[n * 512 + (h0i >> 1)] = hi;
        g_hclo[n * 512 + (h0i >> 1)] = lo;
        split_pair(mean4[2], mean4[3], hi, lo);
        g_hchi[n * 512 + (h0i >> 1) + 1] = hi;
        g_hclo[n * 512 + (h0i >> 1) + 1] = lo;
    }
}

// ---------------- xwx operand preps -------------------------------------------
__global__ void xprep_kernel(const int* __restrict__ cap,
                             const float* __restrict__ We) {
    int gid = blockIdx.x * blockDim.x + threadIdx.x;
    for (int idx = gid; idx < 2048 * 160; idx += 65536) {
        int row = idx / 160, kp = idx % 160;
        int k0 = kp * 2;
        int c = cap[row];
        float x0 = (k0 < WD) ? We[(size_t)c * WD + k0] : 0.f;
        float x1 = (k0 + 1 < WD) ? We[(size_t)c * WD + k0 + 1] : 0.f;
        u32 hi, lo;
        split_pair(x0, x1, hi, lo);
        g_Xhi[idx] = hi;
        g_Xlo[idx] = lo;
    }
}

__global__ void wxprep_kernel(const float* __restrict__ Wx) {
    int gid = blockIdx.x * blockDim.x + threadIdx.x;
    for (int idx = gid; idx < 2048 * 160; idx += 65536) {
        int kp = idx / 2048, j = idx % 2048;
        int k0 = kp * 2;
        float x0 = (k0 < WD) ? Wx[(size_t)k0 * FH + j] : 0.f;
        float x1 = (k0 + 1 < WD) ? Wx[(size_t)(k0 + 1) * FH + j] : 0.f;
        u32 hi, lo;
        split_pair(x0, x1, hi, lo);
        g_WXhi[j * 160 + kp] = hi;
        g_WXlo[j * 160 + kp] = lo;
    }
}

// ---------------- xwx = X @ Wx + b via bf16x3 mma ----------------------------
// C[2048, 2048]; block tile 128x128, 8 warps (2M x 4N), warp 64x32; K=320
#define XA_HI 0
#define XA_LO 5632
#define XB_HI 11264
#define XB_LO 16896
#define XWX_SMEM (22528 * 4)

__global__ __launch_bounds__(256, 1)
void xwx_mma_kernel(const float* __restrict__ bias) {
    extern __shared__ u32 xsm[];
    const int tid = threadIdx.x;
    const int bn = blockIdx.x, bm = blockIdx.y;
    const int warp = tid >> 5, lane = tid & 31;
    const int wm2 = (warp & 1) * 64;
    const int wn2 = (warp >> 1) * 32;
    const int gr = lane >> 2, ct = lane & 3;

    float acc[4][4][4];
    #pragma unroll
    for (int i = 0; i < 4; i++)
        #pragma unroll
        for (int j = 0; j < 4; j++)
            #pragma unroll
            for (int q = 0; q < 4; q++) acc[i][j][q] = 0.f;

    const int srow = tid >> 1;
    const int skq  = (tid & 1) * 20;
    const u32* aH = g_Xhi  + (size_t)(bm * 128 + srow) * 160 + skq;
    const u32* aL = g_Xlo  + (size_t)(bm * 128 + srow) * 160 + skq;
    const u32* bH = g_WXhi + (size_t)(bn * 128 + srow) * 160 + skq;
    const u32* bL = g_WXlo + (size_t)(bn * 128 + srow) * 160 + skq;

    for (int it = 0; it < 4; ++it) {
        #pragma unroll
        for (int q = 0; q < 5; q++) {
            int so = it * 40 + q * 4;
            int dof = srow * 44 + skq + q * 4;
            *(uint4*)&xsm[XA_HI + dof] = *(const uint4*)(aH + so);
            *(uint4*)&xsm[XA_LO + dof] = *(const uint4*)(aL + so);
            *(uint4*)&xsm[XB_HI + dof] = *(const uint4*)(bH + so);
            *(uint4*)&xsm[XB_LO + dof] = *(const uint4*)(bL + so);
        }
        __syncthreads();
        #pragma unroll
        for (int q = 0; q < 5; q++) {
            const int kb = q * 8 + ct;
            u32 ah[4][4], al[4][4];
            #pragma unroll
            for (int i = 0; i < 4; i++) {
                int base = (wm2 + i * 16 + gr) * 44 + kb;
                ah[i][0] = xsm[XA_HI + base];
                ah[i][1] = xsm[XA_HI + base + 8 * 44];
                ah[i][2] = xsm[XA_HI + base + 4];
                ah[i][3] = xsm[XA_HI + base + 8 * 44 + 4];
                al[i][0] = xsm[XA_LO + base];
                al[i][1] = xsm[XA_LO + base + 8 * 44];
                al[i][2] = xsm[XA_LO + base + 4];
                al[i][3] = xsm[XA_LO + base + 8 * 44 + 4];
            }
            #pragma unroll
            for (int j = 0; j < 4; j++) {
                int bbse = (wn2 + j * 8 + gr) * 44 + kb;
                u32 bh0 = xsm[XB_HI + bbse], bh1 = xsm[XB_HI + bbse + 4];
                u32 bl0 = xsm[XB_LO + bbse], bl1 = xsm[XB_LO + bbse + 4];
                #pragma unroll
                for (int i = 0; i < 4; i++) {
                    MMA_BF16(acc[i][j][0], acc[i][j][1], acc[i][j][2], acc[i][j][3],
                             ah[i][0], ah[i][1], ah[i][2], ah[i][3], bh0, bh1);
                    MMA_BF16(acc[i][j][0], acc[i][j][1], acc[i][j][2], acc[i][j][3],
                             ah[i][0], ah[i][1], ah[i][2], ah[i][3], bl0, bl1);
                    MMA_BF16(acc[i][j][0], acc[i][j][1], acc[i][j][2], acc[i][j][3],
                             al[i][0], al[i][1], al[i][2], al[i][3], bh0, bh1);
                }
            }
        }
        __syncthreads();
    }

    #pragma unroll
    for (int i = 0; i < 4; i++) {
        const int r0 = bm * 128 + wm2 + i * 16 + gr;
        #pragma unroll
        for (int j = 0; j < 4; j++) {
            const int col = bn * 128 + wn2 + j * 8 + ct * 2;
            const float b0 = bias[col], b1 = bias[col + 1];
            float2 v0 = {acc[i][j][0] + b0, acc[i][j][1] + b1};
            float2 v1 = {acc[i][j][2] + b0, acc[i][j][3] + b1};
            *(float2*)(g_xwx + (size_t)r0 * FH + col) = v0;
            *(float2*)(g_xwx + (size_t)(r0 + 8) * FH + col) = v1;
        }
    }
}

// ---------------- weight prep: split + transpose into per-block layout --------
__global__ void wprep_kernel(const float* __restrict__ Wh,
                             const float* __restrict__ Wattn) {
    __shared__ float Wt[64][36];
    const int b = blockIdx.x;
    const int ch = blockIdx.y;
    const int tid = threadIdx.x;

    {
        int kk = tid >> 2;
        int g = tid & 3;
        const float* src = (ch < 8)
            ? (Wh + (size_t)(ch * 64 + kk) * FH + g * HD + b * 8)
            : (Wattn + (size_t)((ch - 8) * 64 + kk) * FH + g * HD + b * 8);
        float4 v0 = *(const float4*)(src);
        float4 v1 = *(const float4*)(src + 4);
        *(float4*)&Wt[kk][g * 8]     = v0;
        *(float4*)&Wt[kk][g * 8 + 4] = v1;
    }
    __syncthreads();
    {
        int jj = tid >> 3;
        int kpl = (tid & 7) * 4;
        uint4 vh, vl;
        u32* ph = (u32*)&vh;
        u32* pl = (u32*)&vl;
        #pragma unroll
        for (int q = 0; q < 4; q++) {
            int kp = kpl + q;
            float x0 = Wt[2 * kp][jj];
            float x1 = Wt[2 * kp + 1][jj];
            split_pair(x0, x1, ph[q], pl[q]);
        }
        size_t dst = (size_t)(b * 32 + jj) * 512 + ch * 32 + kpl;
        *(uint4*)(g_Wbhi + dst) = vh;
        *(uint4*)(g_Wblo + dst) = vl;
    }
}

// ---------------- persistent LSTM: 64 blocks x 512 threads --------------------
// chunks of 128 k (64 kp), cp.async 2-buf pipeline (1 sync/chunk), ldmatrix A
#define OFF_BHI  0
#define OFF_BLO  16512
#define OFF_AHI  33024          // 2 bufs x (64 x 68)
#define OFF_ALO  41728
#define OFF_CS   50432          // f32 [64][34]
#define OFF_CELL 52608
#define OFF_HS   53120
#define OFF_RED  53632
#define OFF_WSF  54144
#define LSTM_SMEM (54160 * 4)

__global__ __launch_bounds__(512, 1) void lstm_kernel() {
    extern __shared__ u32 smu[];
    float* smf = (float*)smu;
    const int b = blockIdx.x;
    const int tid = threadIdx.x;
    const unsigned sbase = (unsigned)__cvta_generic_to_shared(smu);

    const int warp = tid >> 5, lane = tid & 31;
    const int wm = (warp & 3) * 16;      // C row base (batch)
    const int wn = (warp >> 2) * 8;      // C col base (j)
    const int gr = lane >> 2, ct = lane & 3;

    // preload weights (hi/lo, stride 516)
    {
        const u32* srcH = g_Wbhi + (size_t)b * 16384;
        const u32* srcL = g_Wblo + (size_t)b * 16384;
        #pragma unroll
        for (int r = 0; r < 8; r++) {
            int idx = r * 2048 + tid * 4;
            int j = idx >> 9, kp = idx & 511;
            *(uint4*)(smu + OFF_BHI + j * 516 + kp) = *(const uint4*)(srcH + idx);
            *(uint4*)(smu + OFF_BLO + j * 516 + kp) = *(const uint4*)(srcL + idx);
        }
    }
    // cell state init: thread -> (n = tid>>3, hl = tid&7)
    {
        int n = tid >> 3, hl = tid & 7;
        smf[OFF_CELL + tid] = g_h0[n * HD + b * 8 + hl];
    }
    __syncthreads();

    // cp.async staging map: thread -> (row = tid>>3, kp octet = (tid&7)*8)
    const int arow = tid >> 3;
    const int akq = (tid & 7) * 8;
    const u32* aSrcHi = g_hchi + arow * 512 + akq;
    const u32* aSrcLo = g_hclo + arow * 512 + akq;
    const unsigned aDstHi = sbase + (OFF_AHI + arow * 68 + akq) * 4;
    const unsigned aDstLo = sbase + (OFF_ALO + arow * 68 + akq) * 4;

    // ldmatrix lane map: mats {rows 0-7/8-15} x {kp +0/+4}
    const int lrow = wm + ((lane >> 3) & 1) * 8 + (lane & 7);
    const int lkp = (lane >> 4) * 4;
    const unsigned aFragHi = sbase + (OFF_AHI + lrow * 68 + lkp) * 4;
    const unsigned aFragLo = sbase + (OFF_ALO + lrow * 68 + lkp) * 4;
    const int jrowH = OFF_BHI + (wn + gr) * 516;
    const int jrowL = OFF_BLO + (wn + gr) * 516;

    unsigned gen = 0;

    for (int t = 0; t < TT; t++) {
        // ---------- stage A: attention for n = b ----------
        {
            const int n = b;
            const float* hp = (t == 0) ? (g_h0 + n * HD)
                                       : (g_hn + (size_t)(n * TT + (t - 1)) * HD);
            smf[OFF_HS + tid] = hp[tid];
            __syncthreads();
            {   // scores: 32 h-slices of 16 x 16 p
                int p = tid & 15, sl = tid >> 4;
                float s = 0.f;
                const float* af = g_Aflat + (size_t)(n * HD + sl * 16) * PP + p;
                const float* hv = &smf[OFF_HS + sl * 16];
                #pragma unroll 4
                for (int h = 0; h < 16; h++) s += hv[h] * af[h * PP];
                smf[OFF_RED + sl * 16 + p] = s;
            }
            __syncthreads();
            if (tid < 32) {   // reduce + softmax in one warp
                int p = tid & 15, half = tid >> 4;
                float s = 0.f;
                #pragma unroll
                for (int i = 0; i < 16; i++)
                    s += smf[OFF_RED + (half * 16 + i) * 16 + p];
                s += __shfl_xor_sync(0xffffffffu, s, 16);
                s *= 0.044194173824159216f;  // 1/sqrt(512)
                float m = s;
                #pragma unroll
                for (int d = 1; d < 16; d <<= 1)
                    m = fmaxf(m, __shfl_xor_sync(0xffffffffu, m, d));
                float e = expf(s - m);
                float sum = e;
                #pragma unroll
                for (int d = 1; d < 16; d <<= 1)
                    sum += __shfl_xor_sync(0xffffffffu, sum, d);
                if (half == 0) smf[OFF_WSF + p] = e / sum;
            }
            __syncthreads();
            if (tid < 256) {   // apply: 2 h per thread -> packed split pair
                float4 w0 = *(const float4*)&smf[OFF_WSF + 0];
                float4 w1 = *(const float4*)&smf[OFF_WSF + 4];
                float4 w2 = *(const float4*)&smf[OFF_WSF + 8];
                float4 w3 = *(const float4*)&smf[OFF_WSF + 12];
                float sv[2];
                #pragma unroll
                for (int r = 0; r < 2; r++) {
                    int h = tid * 2 + r;
                    const float4* af = (const float4*)(g_Aflat + (size_t)(n * HD + h) * PP);
                    float4 x0 = af[0], x1 = af[1], x2 = af[2], x3 = af[3];
                    sv[r] = x0.x * w0.x + x0.y * w0.y + x0.z * w0.z + x0.w * w0.w
                          + x1.x * w1.x + x1.y * w1.y + x1.z * w1.z + x1.w * w1.w
                          + x2.x * w2.x + x2.y * w2.y + x2.z * w2.z + x2.w * w2.w
                          + x3.x * w3.x + x3.y * w3.y + x3.z * w3.z + x3.w * w3.w;
                }
                u32 hi, lo;
                split_pair(sv[0], sv[1], hi, lo);
                g_hchi[n * 512 + 256 + tid] = hi;
                g_hclo[n * 512 + 256 + tid] = lo;
            }
        }
        grid_bar(&gen);

        // ---------- stage B: C[64, 32] = hcat @ Wslice (bf16x3 mma) ----------
        float acc0 = 0.f, acc1 = 0.f, acc2 = 0.f, acc3 = 0.f;

        // prologue: chunk 0 -> buf 0
        CP_ASYNC16(aDstHi, aSrcHi);
        CP_ASYNC16(aDstHi + 16, aSrcHi + 4);
        CP_ASYNC16(aDstLo, aSrcLo);
        CP_ASYNC16(aDstLo + 16, aSrcLo + 4);
        CP_COMMIT();

        for (int it = 0; it < 8; ++it) {
            CP_WAIT0();
            __syncthreads();
            if (it < 7) {
                const unsigned bo = ((it + 1) & 1) * 17408u;
                const u32* sh = aSrcHi + (it + 1) * 64;
                const u32* sl = aSrcLo + (it + 1) * 64;
                CP_ASYNC16(aDstHi + bo, sh);
                CP_ASYNC16(aDstHi + bo + 16, sh + 4);
                CP_ASYNC16(aDstLo + bo, sl);
                CP_ASYNC16(aDstLo + bo + 16, sl + 4);
                CP_COMMIT();
            }
            const unsigned bofs = (it & 1) * 17408u;
            const int kbase = it * 64;
            #pragma unroll
            for (int q = 0; q < 8; q++) {
                u32 ah0, ah1, ah2, ah3, al0, al1, al2, al3;
                LDSM4(ah0, ah1, ah2, ah3, aFragHi + bofs + q * 32);
                LDSM4(al0, al1, al2, al3, aFragLo + bofs + q * 32);
                const int kb = kbase + q * 8 + ct;
                u32 bh0 = smu[jrowH + kb], bh1 = smu[jrowH + kb + 4];
                u32 bl0 = smu[jrowL + kb], bl1 = smu[jrowL + kb + 4];
                MMA_BF16(acc0, acc1, acc2, acc3, ah0, ah1, ah2, ah3, bh0, bh1);
                MMA_BF16(acc0, acc1, acc2, acc3, ah0, ah1, ah2, ah3, bl0, bl1);
                MMA_BF16(acc0, acc1, acc2, acc3, al0, al1, al2, al3, bh0, bh1);
            }
        }

        // epilogue: park C in smem
        {
            float* C = &smf[OFF_CS];
            *(float2*)&C[(wm + gr) * 34 + wn + 2 * ct]     = make_float2(acc0, acc1);
            *(float2*)&C[(wm + gr + 8) * 34 + wn + 2 * ct] = make_float2(acc2, acc3);
        }
        __syncthreads();

        // gates: thread -> (n = tid>>3, hl = tid&7)
        {
            const int n = tid >> 3, hl = tid & 7;
            const float* C = &smf[OFF_CS + n * 34];
            const float* xw = g_xwx + (size_t)(n * TT + t) * FH + b * 8 + hl;
            float ai  = C[hl]      + xw[0];
            float af_ = C[8 + hl]  + xw[HD];
            float ao  = C[16 + hl] + xw[2 * HD];
            float ag  = C[24 + hl] + xw[3 * HD];
            float ig = 1.f / (1.f + expf(-ai));
            float fg = 1.f / (1.f + expf(-af_));
            float og = 1.f / (1.f + expf(-ao));
            float gg = tanhf(ag);
            float c = fg * smf[OFF_CELL + tid] + ig * gg;
            smf[OFF_CELL + tid] = c;
            float h = og * tanhf(c);
            g_hn[(size_t)(n * TT + t) * HD + b * 8 + hl] = h;
            float h1 = __shfl_down_sync(0xffffffffu, h, 1);
            if ((hl & 1) == 0) {
                u32 hi, lo;
                split_pair(h, h1, hi, lo);
                int kp = b * 4 + (hl >> 1);
                g_hchi[n * 512 + kp] = hi;
                g_hclo[n * 512 + kp] = lo;
            }
        }
        grid_bar(&gen);
    }
}

// ---------------- vocab GEMM via tf32 mma.sync, 128x256 tile -----------------
#define ASTR 20
#define BSTR 264
#define VOC_SMEM ((2 * 128 * ASTR + 2 * 16 * BSTR) * 4)
#define AS(bu, m, k) vsm[(bu) * (128 * ASTR) + (m) * ASTR + (k)]
#define BS(bu, k, n) vsm[2 * 128 * ASTR + (bu) * (16 * BSTR) + (k) * BSTR + (n)]

__global__ __launch_bounds__(256, 1)
void vocab_mma_kernel(const float* __restrict__ Wv,
                      const float* __restrict__ bv,
                      float* __restrict__ out) {
    extern __shared__ float vsm[];
    const int tid = threadIdx.x;
    const int bx = blockIdx.x;
    const int by = blockIdx.y;
    const int warp = tid >> 5;
    const int lane = tid & 31;
    const int wm = (warp & 1) * 64;
    const int wn = (warp >> 1) * 64;
    const int gr = lane >> 2;
    const int ct = lane & 3;

    float acc[4][8][4];
    #pragma unroll
    for (int i = 0; i < 4; i++)
        #pragma unroll
        for (int j = 0; j < 8; j++)
            #pragma unroll
            for (int q = 0; q < 4; q++) acc[i][j][q] = 0.f;

    const int arow = tid >> 1;
    const int akq  = (tid & 1) * 8;
    const int bk   = tid >> 4;
    const int bnb  = (tid & 15) * 16;
    const float* aptr = g_hn + (size_t)(by * 128 + arow) * HD + akq;
    const float* bptr = Wv + (size_t)bk * VV + bx * 256 + bnb;

    float4 ar0, ar1, br[4];

    ar0 = *(const float4*)(aptr);
    ar1 = *(const float4*)(aptr + 4);
    #pragma unroll
    for (int c = 0; c < 4; c++) br[c] = *(const float4*)(bptr + c * 4);
    {
        float4 w0, w1;
        w0.x = __uint_as_float(f2tf32(ar0.x)); w0.y = __uint_as_float(f2tf32(ar0.y));
        w0.z = __uint_as_float(f2tf32(ar0.z)); w0.w = __uint_as_float(f2tf32(ar0.w));
        w1.x = __uint_as_float(f2tf32(ar1.x)); w1.y = __uint_as_float(f2tf32(ar1.y));
        w1.z = __uint_as_float(f2tf32(ar1.z)); w1.w = __uint_as_float(f2tf32(ar1.w));
        *(float4*)&AS(0, arow, akq) = w0;
        *(float4*)&AS(0, arow, akq + 4) = w1;
        #pragma unroll
        for (int c = 0; c < 4; c++) {
            float4 w;
            w.x = __uint_as_float(f2tf32(br[c].x)); w.y = __uint_as_float(f2tf32(br[c].y));
            w.z = __uint_as_float(f2tf32(br[c].z)); w.w = __uint_as_float(f2tf32(br[c].w));
            *(float4*)&BS(0, bk, bnb + c * 4) = w;
        }
    }
    __syncthreads();

    for (int it = 0; it < 32; ++it) {
        if (it < 31) {
            int k0 = (it + 1) * 16;
            ar0 = *(const float4*)(aptr + k0);
            ar1 = *(const float4*)(aptr + k0 + 4);
            #pragma unroll
            for (int c = 0; c < 4; c++)
                br[c] = *(const float4*)(bptr + (size_t)k0 * VV + c * 4);
        }
        const int cb = it & 1;
        #pragma unroll
        for (int ks = 0; ks < 2; ks++) {
            const int kb = ks * 8;
            unsigned a[4][4], bb[8][2];
            #pragma unroll
            for (int i = 0; i < 4; i++) {
                const int mr = wm + i * 16 + gr;
                a[i][0] = __float_as_uint(AS(cb, mr,     kb + ct));
                a[i][1] = __float_as_uint(AS(cb, mr + 8, kb + ct));
                a[i][2] = __float_as_uint(AS(cb, mr,     kb + ct + 4));
                a[i][3] = __float_as_uint(AS(cb, mr + 8, kb + ct + 4));
            }
            #pragma unroll
            for (int j = 0; j < 8; j++) {
                const int nb = wn + j * 8 + gr;
                bb[j][0] = __float_as_uint(BS(cb, kb + ct,     nb));
                bb[j][1] = __float_as_uint(BS(cb, kb + ct + 4, nb));
            }
            #pragma unroll
            for (int i = 0; i < 4; i++)
                #pragma unroll
                for (int j = 0; j < 8; j++) {
                    asm volatile(
                        "mma.sync.aligned.m16n8k8.row.col.f32.tf32.tf32.f32 "
                        "{%0,%1,%2,%3}, {%4,%5,%6,%7}, {%8,%9}, {%0,%1,%2,%3};\n"
                        : "+f"(acc[i][j][0]), "+f"(acc[i][j][1]),
                          "+f"(acc[i][j][2]), "+f"(acc[i][j][3])
                        : "r"(a[i][0]), "r"(a[i][1]), "r"(a[i][2]), "r"(a[i][3]),
                          "r"(bb[j][0]), "r"(bb[j][1]));
                }
        }
        if (it < 31) {
            const int nb = (it + 1) & 1;
            float4 w0, w1;
            w0.x = __uint_as_float(f2tf32(ar0.x)); w0.y = __uint_as_float(f2tf32(ar0.y));
            w0.z = __uint_as_float(f2tf32(ar0.z)); w0.w = __uint_as_float(f2tf32(ar0.w));
            w1.x = __uint_as_float(f2tf32(ar1.x)); w1.y = __uint_as_float(f2tf32(ar1.y));
            w1.z = __uint_as_float(f2tf32(ar1.z)); w1.w = __uint_as_float(f2tf32(ar1.w));
            *(float4*)&AS(nb, arow, akq) = w0;
            *(float4*)&AS(nb, arow, akq + 4) = w1;
            #pragma unroll
            for (int c = 0; c < 4; c++) {
                float4 w;
                w.x = __uint_as_float(f2tf32(br[c].x)); w.y = __uint_as_float(f2tf32(br[c].y));
                w.z = __uint_as_float(f2tf32(br[c].z)); w.w = __uint_as_float(f2tf32(br[c].w));
                *(float4*)&BS(nb, bk, bnb + c * 4) = w;
            }
        }
        __syncthreads();
    }

    #pragma unroll
    for (int i = 0; i < 4; i++) {
        const int r0 = by * 128 + wm + i * 16 + gr;
        #pragma unroll
        for (int j = 0; j < 8; j++) {
            const int col = bx * 256 + wn + j * 8 + ct * 2;
            const float b0 = bv[col], b1 = bv[col + 1];
            float2 v0 = {acc[i][j][0] + b0, acc[i][j][1] + b1};
            float2 v1 = {acc[i][j][2] + b0, acc[i][j][3] + b1};
            *(float2*)(out + (size_t)r0 * VV + col) = v0;
            *(float2*)(out + (size_t)(r0 + 8) * VV + col) = v1;
        }
    }
}

// ---------------- launch ------------------------------------------------------
extern "C" void kernel_launch(void* const* d_in, const int* in_sizes, int n_in,
                              void* d_out, int out_size) {
    const float* A      = (const float*)d_in[0];
    const int*   cap    = (const int*)d_in[1];
    const float* conv_w = (const float*)d_in[2];
    const float* conv_b = (const float*)d_in[3];
    const float* Wx     = (const float*)d_in[4];
    const float* Wh     = (const float*)d_in[5];
    const float* Wattn  = (const float*)d_in[6];
    const float* b      = (const float*)d_in[7];
    const float* We     = (const float*)d_in[8];
    const float* Wv     = (const float*)d_in[9];
    const float* bv     = (const float*)d_in[10];
    float* out = (float*)d_out;

    cudaFuncSetAttribute(vocab_mma_kernel,
                         cudaFuncAttributeMaxDynamicSharedMemorySize, VOC_SMEM);
    cudaFuncSetAttribute(lstm_kernel,
                         cudaFuncAttributeMaxDynamicSharedMemorySize, LSTM_SMEM);
    cudaFuncSetAttribute(xwx_mma_kernel,
                         cudaFuncAttributeMaxDynamicSharedMemorySize, XWX_SMEM);

    conv_kernel<<<dim3(64, 8), 256>>>(A, conv_w, conv_b);
    xprep_kernel<<<256, 256>>>(cap, We);
    wxprep_kernel<<<256, 256>>>(Wx);
    xwx_mma_kernel<<<dim3(16, 16), 256, XWX_SMEM>>>(b);
    wprep_kernel<<<dim3(64, 16), 256>>>(Wh, Wattn);
    lstm_kernel<<<NBLK, 512, LSTM_SMEM>>>();
    vocab_mma_kernel<<<dim3(125, 16), 256, VOC_SMEM>>>(Wv, bv, out);
}